// round 6
// baseline (speedup 1.0000x reference)
#include <cuda_runtime.h>
#include <math.h>

#define Hd      128
#define Ld      200
#define DTd     768
#define DId     512
#define Ed      8
#define NTOK    25600
#define TB      64
#define NTHREADS 256
#define KC      32
#define SWROW   128   // floats per swizzled weight k-row
#define SA      36    // gathered-A chunk row stride
#define SX      132   // persistent activation row stride

// shared memory layout (float offsets)
#define OFF_W   0                      // 32*128 = 4096
#define OFF_A   4096                   // 64*36  = 2304
#define OFF_X   6400                   // 64*132 = 8448
#define OFF_Y   14848                  // 8448
#define OFF_GT  23296                  // 512
#define OFF_GI  23808                  // 512
#define OFF_IDS 24320                  // 64
#define SMEM_FLOATS 24384              // 97536 bytes -> 2 CTAs/SM

__device__ __forceinline__ float hreduce16(float v) {
    v += __shfl_xor_sync(0xffffffffu, v, 1);
    v += __shfl_xor_sync(0xffffffffu, v, 2);
    v += __shfl_xor_sync(0xffffffffu, v, 4);
    v += __shfl_xor_sync(0xffffffffu, v, 8);
    return v;
}

// Load a [128 x KC=32] weight chunk into smem, transposed + XOR-swizzled:
// element (k, h) lives at sW[k*128 + ((h>>2) ^ ((k>>2)&7))*4 + (h&3)].
// Stores hit all 32 banks (conflict-free); reads are 16B-aligned permutations.
__device__ __forceinline__ void load_w_chunk(const float* __restrict__ Wg, int ldw, int kc,
                                             float* __restrict__ sW, int tid) {
#pragma unroll
    for (int j = 0; j < 4; ++j) {
        int idx = tid + j * NTHREADS;          // 0..1023 float4 slots
        int h   = idx >> 3;                    // 0..127
        int k4  = (idx & 7) * 4;               // 0..28
        float4 v = *reinterpret_cast<const float4*>(Wg + (long)h * ldw + kc + k4);
        int m  = (k4 >> 2) & 7;
        int fb = (((h >> 2) ^ m) << 2) + (h & 3);
        float* dst = sW + k4 * SWROW + fb;
        dst[0 * SWROW] = v.x;
        dst[1 * SWROW] = v.y;
        dst[2 * SWROW] = v.z;
        dst[3 * SWROW] = v.w;
    }
}

// Gather [64 x 32] activation chunk from an embedding table into sA.
__device__ __forceinline__ void gather_a_chunk(const float* __restrict__ table, int ldw, int kc,
                                               const int* __restrict__ sids,
                                               float* __restrict__ sA, int tid) {
#pragma unroll
    for (int j = 0; j < 2; ++j) {
        int idx = tid + j * NTHREADS;          // 0..511 float4 slots
        int t  = idx >> 3;
        int kq = (idx & 7) * 4;
        float4 v = *reinterpret_cast<const float4*>(table + (long)sids[t] * ldw + kc + kq);
        *reinterpret_cast<float4*>(sA + t * SA + kq) = v;
    }
}

// 4 tokens x 8 outputs (h = tx*4+{0..3} and tx*4+64+{0..3}), KC=32, swizzled W reads.
__device__ __forceinline__ void gemm_chunk4(const float* __restrict__ a0,
                                            const float* __restrict__ a1,
                                            const float* __restrict__ a2,
                                            const float* __restrict__ a3,
                                            const float* __restrict__ sW,
                                            int tx, float acc[4][8]) {
#pragma unroll
    for (int k4 = 0; k4 < KC; k4 += 4) {
        const int m = (k4 >> 2) & 7;
        const float* wlo = sW + k4 * SWROW + ((tx ^ m) << 2);
        float4 A0 = *reinterpret_cast<const float4*>(a0 + k4);
        float4 A1 = *reinterpret_cast<const float4*>(a1 + k4);
        float4 A2 = *reinterpret_cast<const float4*>(a2 + k4);
        float4 A3 = *reinterpret_cast<const float4*>(a3 + k4);
        float av[4][4] = {{A0.x, A0.y, A0.z, A0.w}, {A1.x, A1.y, A1.z, A1.w},
                          {A2.x, A2.y, A2.z, A2.w}, {A3.x, A3.y, A3.z, A3.w}};
#pragma unroll
        for (int kk = 0; kk < 4; ++kk) {
            float4 b0 = *reinterpret_cast<const float4*>(wlo + kk * SWROW);
            float4 b1 = *reinterpret_cast<const float4*>(wlo + kk * SWROW + 64);
            float b[8] = {b0.x, b0.y, b0.z, b0.w, b1.x, b1.y, b1.z, b1.w};
#pragma unroll
            for (int p = 0; p < 4; ++p)
#pragma unroll
                for (int j = 0; j < 8; ++j)
                    acc[p][j] = fmaf(av[p][kk], b[j], acc[p][j]);
        }
    }
}

// 2 tokens x 8 outputs (VAE half-passes).
__device__ __forceinline__ void gemm_chunk2(const float* __restrict__ a0,
                                            const float* __restrict__ a1,
                                            const float* __restrict__ sW,
                                            int tx, float acc[2][8]) {
#pragma unroll
    for (int k4 = 0; k4 < KC; k4 += 4) {
        const int m = (k4 >> 2) & 7;
        const float* wlo = sW + k4 * SWROW + ((tx ^ m) << 2);
        float4 A0 = *reinterpret_cast<const float4*>(a0 + k4);
        float4 A1 = *reinterpret_cast<const float4*>(a1 + k4);
        float av[2][4] = {{A0.x, A0.y, A0.z, A0.w}, {A1.x, A1.y, A1.z, A1.w}};
#pragma unroll
        for (int kk = 0; kk < 4; ++kk) {
            float4 b0 = *reinterpret_cast<const float4*>(wlo + kk * SWROW);
            float4 b1 = *reinterpret_cast<const float4*>(wlo + kk * SWROW + 64);
            float b[8] = {b0.x, b0.y, b0.z, b0.w, b1.x, b1.y, b1.z, b1.w};
#pragma unroll
            for (int j = 0; j < 8; ++j) {
                acc[0][j] = fmaf(av[0][kk], b[j], acc[0][j]);
                acc[1][j] = fmaf(av[1][kk], b[j], acc[1][j]);
            }
        }
    }
}

// 1 token x 8 outputs, gate folded into A (expert stage).
__device__ __forceinline__ void gemm_gated(const float* __restrict__ a, float g,
                                           const float* __restrict__ sW,
                                           int tx, float acc[8]) {
#pragma unroll
    for (int k4 = 0; k4 < KC; k4 += 4) {
        const int m = (k4 >> 2) & 7;
        const float* wlo = sW + k4 * SWROW + ((tx ^ m) << 2);
        float4 A0 = *reinterpret_cast<const float4*>(a + k4);
        float av[4] = {A0.x * g, A0.y * g, A0.z * g, A0.w * g};
#pragma unroll
        for (int kk = 0; kk < 4; ++kk) {
            float4 b0 = *reinterpret_cast<const float4*>(wlo + kk * SWROW);
            float4 b1 = *reinterpret_cast<const float4*>(wlo + kk * SWROW + 64);
            acc[0] = fmaf(av[kk], b0.x, acc[0]);
            acc[1] = fmaf(av[kk], b0.y, acc[1]);
            acc[2] = fmaf(av[kk], b0.z, acc[2]);
            acc[3] = fmaf(av[kk], b0.w, acc[3]);
            acc[4] = fmaf(av[kk], b1.x, acc[4]);
            acc[5] = fmaf(av[kk], b1.y, acc[5]);
            acc[6] = fmaf(av[kk], b1.z, acc[6]);
            acc[7] = fmaf(av[kk], b1.w, acc[7]);
        }
    }
}

// softmax over 8 -> keep top-2 (earliest index on ties) -> renorm
__device__ __forceinline__ void route8(float* g) {
    float m = g[0];
#pragma unroll
    for (int e = 1; e < Ed; ++e) m = fmaxf(m, g[e]);
    float ex[Ed]; float s = 0.f;
#pragma unroll
    for (int e = 0; e < Ed; ++e) { ex[e] = __expf(g[e] - m); s += ex[e]; }
    float inv = 1.f / s;
#pragma unroll
    for (int e = 0; e < Ed; ++e) ex[e] *= inv;
    int i1 = 0; float w1 = ex[0];
#pragma unroll
    for (int e = 1; e < Ed; ++e) if (ex[e] > w1) { w1 = ex[e]; i1 = e; }
    int i2 = -1; float w2 = -1.f;
#pragma unroll
    for (int e = 0; e < Ed; ++e) if (e != i1 && ex[e] > w2) { w2 = ex[e]; i2 = e; }
    float den = 1.f / (w1 + w2 + 1e-8f);
#pragma unroll
    for (int e = 0; e < Ed; ++e)
        g[e] = (e == i1) ? w1 * den : ((e == i2) ? w2 * den : 0.f);
}

__global__ __launch_bounds__(NTHREADS, 2)
void sasrec_fused_kernel(
    const int*   __restrict__ input_ids,
    const float* __restrict__ t_noise,   const float* __restrict__ i_noise,
    const float* __restrict__ item_table,const float* __restrict__ pos_table,
    const float* __restrict__ text_table,const float* __restrict__ img_table,
    const float* __restrict__ fc_text_w, const float* __restrict__ fc_text_b,
    const float* __restrict__ fc_img_w,  const float* __restrict__ fc_img_b,
    const float* __restrict__ ln_w,      const float* __restrict__ ln_b,
    const float* __restrict__ mu_t_w,    const float* __restrict__ mu_t_b,
    const float* __restrict__ sg_t_w,    const float* __restrict__ sg_t_b,
    const float* __restrict__ mu_i_w,    const float* __restrict__ mu_i_b,
    const float* __restrict__ sg_i_w,    const float* __restrict__ sg_i_b,
    const float* __restrict__ gate_w,    const float* __restrict__ gate_b,
    const float* __restrict__ texp_w,    const float* __restrict__ texp_b,
    const float* __restrict__ iexp_w,    const float* __restrict__ iexp_b,
    const float* __restrict__ fus_w,     const float* __restrict__ fus_b,
    const float* __restrict__ fus_ln_w,  const float* __restrict__ fus_ln_b,
    float*       __restrict__ out)
{
    extern __shared__ float sm[];
    float* sW  = sm + OFF_W;
    float* sA  = sm + OFF_A;
    float* sX  = sm + OFF_X;
    float* sY  = sm + OFF_Y;
    float* sgt = sm + OFF_GT;
    float* sgi = sm + OFF_GI;
    int*   sids = (int*)(sm + OFF_IDS);

    const int tid = threadIdx.x;
    const int tx  = tid & 15;
    const int ty  = tid >> 4;          // 0..15
    const int hlo = tx * 4;            // outputs hlo..hlo+3 and hlo+64..hlo+67
    const int n0  = blockIdx.x * TB;

    if (tid < TB) sids[tid] = input_ids[n0 + tid];
    __syncthreads();

    float acc[4][8];

    // ---------------- stage 1: text_emb = l2norm(text_table[ids] @ fc_text_w^T + b) -> sX
    {
#pragma unroll
        for (int p = 0; p < 4; ++p)
#pragma unroll
            for (int j = 0; j < 8; ++j) acc[p][j] = 0.f;
        for (int kc = 0; kc < DTd; kc += KC) {
            __syncthreads();
            gather_a_chunk(text_table, DTd, kc, sids, sA, tid);
            load_w_chunk(fc_text_w, DTd, kc, sW, tid);
            __syncthreads();
            gemm_chunk4(sA + ty * SA, sA + (ty + 16) * SA,
                        sA + (ty + 32) * SA, sA + (ty + 48) * SA, sW, tx, acc);
        }
        float4 blo = *reinterpret_cast<const float4*>(fc_text_b + hlo);
        float4 bhi = *reinterpret_cast<const float4*>(fc_text_b + hlo + 64);
        float bb[8] = {blo.x, blo.y, blo.z, blo.w, bhi.x, bhi.y, bhi.z, bhi.w};
#pragma unroll
        for (int p = 0; p < 4; ++p) {
            int t = ty + 16 * p;
            float ss = 0.f;
#pragma unroll
            for (int j = 0; j < 8; ++j) {
                acc[p][j] += bb[j];
                ss += acc[p][j] * acc[p][j];
            }
            ss = hreduce16(ss);
            float sc = 1.f / fmaxf(sqrtf(ss), 1e-12f);
            float4 olo = {acc[p][0] * sc, acc[p][1] * sc, acc[p][2] * sc, acc[p][3] * sc};
            float4 ohi = {acc[p][4] * sc, acc[p][5] * sc, acc[p][6] * sc, acc[p][7] * sc};
            *reinterpret_cast<float4*>(sX + t * SX + hlo)      = olo;
            *reinterpret_cast<float4*>(sX + t * SX + hlo + 64) = ohi;
        }
    }

    // ---------------- stage 2: img_emb -> sY ----------------
    {
#pragma unroll
        for (int p = 0; p < 4; ++p)
#pragma unroll
            for (int j = 0; j < 8; ++j) acc[p][j] = 0.f;
        for (int kc = 0; kc < DId; kc += KC) {
            __syncthreads();
            gather_a_chunk(img_table, DId, kc, sids, sA, tid);
            load_w_chunk(fc_img_w, DId, kc, sW, tid);
            __syncthreads();
            gemm_chunk4(sA + ty * SA, sA + (ty + 16) * SA,
                        sA + (ty + 32) * SA, sA + (ty + 48) * SA, sW, tx, acc);
        }
        float4 blo = *reinterpret_cast<const float4*>(fc_img_b + hlo);
        float4 bhi = *reinterpret_cast<const float4*>(fc_img_b + hlo + 64);
        float bb[8] = {blo.x, blo.y, blo.z, blo.w, bhi.x, bhi.y, bhi.z, bhi.w};
#pragma unroll
        for (int p = 0; p < 4; ++p) {
            int t = ty + 16 * p;
            float ss = 0.f;
#pragma unroll
            for (int j = 0; j < 8; ++j) {
                acc[p][j] += bb[j];
                ss += acc[p][j] * acc[p][j];
            }
            ss = hreduce16(ss);
            float sc = 1.f / fmaxf(sqrtf(ss), 1e-12f);
            float4 olo = {acc[p][0] * sc, acc[p][1] * sc, acc[p][2] * sc, acc[p][3] * sc};
            float4 ohi = {acc[p][4] * sc, acc[p][5] * sc, acc[p][6] * sc, acc[p][7] * sc};
            *reinterpret_cast<float4*>(sY + t * SX + hlo)      = olo;
            *reinterpret_cast<float4*>(sY + t * SX + hlo + 64) = ohi;
        }
    }

    // ---------------- stage 3: VAE reparam text (two half-token passes) -> sX ----------------
#pragma unroll 1
    for (int q = 0; q < 2; ++q) {
        const int tA = ty + 32 * q;
        float mu2[2][8], sg2[2][8];
#pragma unroll
        for (int p = 0; p < 2; ++p)
#pragma unroll
            for (int j = 0; j < 8; ++j) { mu2[p][j] = 0.f; sg2[p][j] = 0.f; }
        for (int kc = 0; kc < Hd; kc += KC) {
            __syncthreads();
            load_w_chunk(mu_t_w, Hd, kc, sW, tid);
            __syncthreads();
            gemm_chunk2(sX + tA * SX + kc, sX + (tA + 16) * SX + kc, sW, tx, mu2);
        }
        for (int kc = 0; kc < Hd; kc += KC) {
            __syncthreads();
            load_w_chunk(sg_t_w, Hd, kc, sW, tid);
            __syncthreads();
            gemm_chunk2(sX + tA * SX + kc, sX + (tA + 16) * SX + kc, sW, tx, sg2);
        }
        float4 mblo = *reinterpret_cast<const float4*>(mu_t_b + hlo);
        float4 mbhi = *reinterpret_cast<const float4*>(mu_t_b + hlo + 64);
        float4 sblo = *reinterpret_cast<const float4*>(sg_t_b + hlo);
        float4 sbhi = *reinterpret_cast<const float4*>(sg_t_b + hlo + 64);
        float mb[8] = {mblo.x, mblo.y, mblo.z, mblo.w, mbhi.x, mbhi.y, mbhi.z, mbhi.w};
        float sb[8] = {sblo.x, sblo.y, sblo.z, sblo.w, sbhi.x, sbhi.y, sbhi.z, sbhi.w};
#pragma unroll
        for (int p = 0; p < 2; ++p) {
            int t = tA + 16 * p;
            const float* np = t_noise + (long)(n0 + t) * Hd;
            float4 nlo = *reinterpret_cast<const float4*>(np + hlo);
            float4 nhi = *reinterpret_cast<const float4*>(np + hlo + 64);
            float nn[8] = {nlo.x, nlo.y, nlo.z, nlo.w, nhi.x, nhi.y, nhi.z, nhi.w};
            float z[8];
#pragma unroll
            for (int j = 0; j < 8; ++j)
                z[j] = mu2[p][j] + mb[j] + __expf(sg2[p][j] + sb[j]) * nn[j];
            float4 zlo = {z[0], z[1], z[2], z[3]};
            float4 zhi = {z[4], z[5], z[6], z[7]};
            *reinterpret_cast<float4*>(sX + t * SX + hlo)      = zlo;
            *reinterpret_cast<float4*>(sX + t * SX + hlo + 64) = zhi;
        }
    }

    // ---------------- stage 4: VAE reparam img (two half-token passes) -> sY ----------------
#pragma unroll 1
    for (int q = 0; q < 2; ++q) {
        const int tA = ty + 32 * q;
        float mu2[2][8], sg2[2][8];
#pragma unroll
        for (int p = 0; p < 2; ++p)
#pragma unroll
            for (int j = 0; j < 8; ++j) { mu2[p][j] = 0.f; sg2[p][j] = 0.f; }
        for (int kc = 0; kc < Hd; kc += KC) {
            __syncthreads();
            load_w_chunk(mu_i_w, Hd, kc, sW, tid);
            __syncthreads();
            gemm_chunk2(sY + tA * SX + kc, sY + (tA + 16) * SX + kc, sW, tx, mu2);
        }
        for (int kc = 0; kc < Hd; kc += KC) {
            __syncthreads();
            load_w_chunk(sg_i_w, Hd, kc, sW, tid);
            __syncthreads();
            gemm_chunk2(sY + tA * SX + kc, sY + (tA + 16) * SX + kc, sW, tx, sg2);
        }
        float4 mblo = *reinterpret_cast<const float4*>(mu_i_b + hlo);
        float4 mbhi = *reinterpret_cast<const float4*>(mu_i_b + hlo + 64);
        float4 sblo = *reinterpret_cast<const float4*>(sg_i_b + hlo);
        float4 sbhi = *reinterpret_cast<const float4*>(sg_i_b + hlo + 64);
        float mb[8] = {mblo.x, mblo.y, mblo.z, mblo.w, mbhi.x, mbhi.y, mbhi.z, mbhi.w};
        float sb[8] = {sblo.x, sblo.y, sblo.z, sblo.w, sbhi.x, sbhi.y, sbhi.z, sbhi.w};
#pragma unroll
        for (int p = 0; p < 2; ++p) {
            int t = tA + 16 * p;
            const float* np = i_noise + (long)(n0 + t) * Hd;
            float4 nlo = *reinterpret_cast<const float4*>(np + hlo);
            float4 nhi = *reinterpret_cast<const float4*>(np + hlo + 64);
            float nn[8] = {nlo.x, nlo.y, nlo.z, nlo.w, nhi.x, nhi.y, nhi.z, nhi.w};
            float z[8];
#pragma unroll
            for (int j = 0; j < 8; ++j)
                z[j] = mu2[p][j] + mb[j] + __expf(sg2[p][j] + sb[j]) * nn[j];
            float4 zlo = {z[0], z[1], z[2], z[3]};
            float4 zhi = {z[4], z[5], z[6], z[7]};
            *reinterpret_cast<float4*>(sY + t * SX + hlo)      = zlo;
            *reinterpret_cast<float4*>(sY + t * SX + hlo + 64) = zhi;
        }
    }

    // ---------------- stage 5: gating (both modalities) ----------------
    __syncthreads();
    {
        int t  = tid >> 2;            // 0..63
        int e0 = (tid & 3) * 2;       // each thread: experts e0, e0+1
#pragma unroll
        for (int qe = 0; qe < 2; ++qe) {
            int e = e0 + qe;
            const float* gw = gate_w + e * Hd;
            float dt = 0.f, di = 0.f;
#pragma unroll 8
            for (int k4 = 0; k4 < Hd; k4 += 4) {
                float4 w = *reinterpret_cast<const float4*>(gw + k4);
                float4 x = *reinterpret_cast<const float4*>(sX + t * SX + k4);
                float4 y = *reinterpret_cast<const float4*>(sY + t * SX + k4);
                dt = fmaf(x.x, w.x, fmaf(x.y, w.y, fmaf(x.z, w.z, fmaf(x.w, w.w, dt))));
                di = fmaf(y.x, w.x, fmaf(y.y, w.y, fmaf(y.z, w.z, fmaf(y.w, w.w, di))));
            }
            sgt[t * Ed + e] = dt + gate_b[e];
            sgi[t * Ed + e] = di + gate_b[e];
        }
    }
    __syncthreads();
    if (tid < TB) {
        route8(sgt + tid * Ed);
        route8(sgi + tid * Ed);
    }
    __syncthreads();

    // ---------------- stage 6: text experts (top-2 sparse, gate folded into A) -> sX ----------------
    {
        float outv[4][8];
#pragma unroll
        for (int p = 0; p < 4; ++p) {
            int t = ty + 16 * p;
#pragma unroll
            for (int j = 0; j < 8; ++j) outv[p][j] = 0.f;
#pragma unroll
            for (int e = 0; e < Ed; ++e) {
                float g = sgt[t * Ed + e];
                if (g != 0.f) {
                    const float* bp = texp_b + e * Hd;
                    float4 blo = *reinterpret_cast<const float4*>(bp + hlo);
                    float4 bhi = *reinterpret_cast<const float4*>(bp + hlo + 64);
                    float bb[8] = {blo.x, blo.y, blo.z, blo.w, bhi.x, bhi.y, bhi.z, bhi.w};
#pragma unroll
                    for (int j = 0; j < 8; ++j)
                        outv[p][j] = fmaf(g, bb[j], outv[p][j]);
                }
            }
        }
#pragma unroll 1
        for (int e = 0; e < Ed; ++e) {
            const float* We = texp_w + (long)e * Hd * Hd;
#pragma unroll 1
            for (int kc = 0; kc < Hd; kc += KC) {
                __syncthreads();
                load_w_chunk(We, Hd, kc, sW, tid);
                __syncthreads();
#pragma unroll
                for (int p = 0; p < 4; ++p) {
                    float g = sgt[(ty + 16 * p) * Ed + e];
                    if (g != 0.f)
                        gemm_gated(sX + (ty + 16 * p) * SX + kc, g, sW, tx, outv[p]);
                }
            }
        }
        __syncthreads();
#pragma unroll
        for (int p = 0; p < 4; ++p) {
            int t = ty + 16 * p;
            float4 olo = {outv[p][0], outv[p][1], outv[p][2], outv[p][3]};
            float4 ohi = {outv[p][4], outv[p][5], outv[p][6], outv[p][7]};
            *reinterpret_cast<float4*>(sX + t * SX + hlo)      = olo;
            *reinterpret_cast<float4*>(sX + t * SX + hlo + 64) = ohi;
        }
    }

    // ---------------- stage 7: img experts -> sY ----------------
    {
        float outv[4][8];
#pragma unroll
        for (int p = 0; p < 4; ++p) {
            int t = ty + 16 * p;
#pragma unroll
            for (int j = 0; j < 8; ++j) outv[p][j] = 0.f;
#pragma unroll
            for (int e = 0; e < Ed; ++e) {
                float g = sgi[t * Ed + e];
                if (g != 0.f) {
                    const float* bp = iexp_b + e * Hd;
                    float4 blo = *reinterpret_cast<const float4*>(bp + hlo);
                    float4 bhi = *reinterpret_cast<const float4*>(bp + hlo + 64);
                    float bb[8] = {blo.x, blo.y, blo.z, blo.w, bhi.x, bhi.y, bhi.z, bhi.w};
#pragma unroll
                    for (int j = 0; j < 8; ++j)
                        outv[p][j] = fmaf(g, bb[j], outv[p][j]);
                }
            }
        }
#pragma unroll 1
        for (int e = 0; e < Ed; ++e) {
            const float* We = iexp_w + (long)e * Hd * Hd;
#pragma unroll 1
            for (int kc = 0; kc < Hd; kc += KC) {
                __syncthreads();
                load_w_chunk(We, Hd, kc, sW, tid);
                __syncthreads();
#pragma unroll
                for (int p = 0; p < 4; ++p) {
                    float g = sgi[(ty + 16 * p) * Ed + e];
                    if (g != 0.f)
                        gemm_gated(sY + (ty + 16 * p) * SX + kc, g, sW, tx, outv[p]);
                }
            }
        }
        __syncthreads();
#pragma unroll
        for (int p = 0; p < 4; ++p) {
            int t = ty + 16 * p;
            float4 olo = {outv[p][0], outv[p][1], outv[p][2], outv[p][3]};
            float4 ohi = {outv[p][4], outv[p][5], outv[p][6], outv[p][7]};
            *reinterpret_cast<float4*>(sY + t * SX + hlo)      = olo;
            *reinterpret_cast<float4*>(sY + t * SX + hlo + 64) = ohi;
        }
    }

    // ---------------- stage 8: fusion + recomputed seq_emb ----------------
    {
#pragma unroll
        for (int p = 0; p < 4; ++p)
#pragma unroll
            for (int j = 0; j < 8; ++j) acc[p][j] = 0.f;
        for (int kc = 0; kc < 2 * Hd; kc += KC) {
            __syncthreads();
            load_w_chunk(fus_w, 2 * Hd, kc, sW, tid);
            __syncthreads();
            const float* base = (kc < Hd) ? sX : sY;
            int ko = (kc < Hd) ? kc : (kc - Hd);
            gemm_chunk4(base + ty * SX + ko, base + (ty + 16) * SX + ko,
                        base + (ty + 32) * SX + ko, base + (ty + 48) * SX + ko,
                        sW, tx, acc);
        }
        float4 fblo = *reinterpret_cast<const float4*>(fus_b + hlo);
        float4 fbhi = *reinterpret_cast<const float4*>(fus_b + hlo + 64);
        float fb[8] = {fblo.x, fblo.y, fblo.z, fblo.w, fbhi.x, fbhi.y, fbhi.z, fbhi.w};
        float4 fwlo = *reinterpret_cast<const float4*>(fus_ln_w + hlo);
        float4 fwhi = *reinterpret_cast<const float4*>(fus_ln_w + hlo + 64);
        float flw[8] = {fwlo.x, fwlo.y, fwlo.z, fwlo.w, fwhi.x, fwhi.y, fwhi.z, fwhi.w};
        float4 fllo = *reinterpret_cast<const float4*>(fus_ln_b + hlo);
        float4 flhi = *reinterpret_cast<const float4*>(fus_ln_b + hlo + 64);
        float flb[8] = {fllo.x, fllo.y, fllo.z, fllo.w, flhi.x, flhi.y, flhi.z, flhi.w};
        float4 lwlo = *reinterpret_cast<const float4*>(ln_w + hlo);
        float4 lwhi = *reinterpret_cast<const float4*>(ln_w + hlo + 64);
        float lw[8] = {lwlo.x, lwlo.y, lwlo.z, lwlo.w, lwhi.x, lwhi.y, lwhi.z, lwhi.w};
        float4 lblo = *reinterpret_cast<const float4*>(ln_b + hlo);
        float4 lbhi = *reinterpret_cast<const float4*>(ln_b + hlo + 64);
        float lb[8] = {lblo.x, lblo.y, lblo.z, lblo.w, lbhi.x, lbhi.y, lbhi.z, lbhi.w};
#pragma unroll
        for (int p = 0; p < 4; ++p) {
            int t = ty + 16 * p;
            int n = n0 + t;
            // fusion LN
            float s = 0.f, sq = 0.f;
#pragma unroll
            for (int j = 0; j < 8; ++j) {
                acc[p][j] += fb[j];
                s += acc[p][j]; sq += acc[p][j] * acc[p][j];
            }
            s  = hreduce16(s);
            sq = hreduce16(sq);
            float mean = s * (1.f / Hd);
            float var  = sq * (1.f / Hd) - mean * mean;
            float inv  = rsqrtf(var + 1e-5f);
            // recompute seq_emb = LN(item + pos)
            int id  = sids[t];
            int pos = n % Ld;
            const float* ip = item_table + (long)id * Hd;
            const float* pp = pos_table + pos * Hd;
            float4 ilo = *reinterpret_cast<const float4*>(ip + hlo);
            float4 ihi = *reinterpret_cast<const float4*>(ip + hlo + 64);
            float4 plo = *reinterpret_cast<const float4*>(pp + hlo);
            float4 phi = *reinterpret_cast<const float4*>(pp + hlo + 64);
            float v[8] = {ilo.x + plo.x, ilo.y + plo.y, ilo.z + plo.z, ilo.w + plo.w,
                          ihi.x + phi.x, ihi.y + phi.y, ihi.z + phi.z, ihi.w + phi.w};
            float s2 = 0.f, sq2 = 0.f;
#pragma unroll
            for (int j = 0; j < 8; ++j) { s2 += v[j]; sq2 += v[j] * v[j]; }
            s2  = hreduce16(s2);
            sq2 = hreduce16(sq2);
            float mean2 = s2 * (1.f / Hd);
            float var2  = sq2 * (1.f / Hd) - mean2 * mean2;
            float inv2  = rsqrtf(var2 + 1e-12f);
            float r[8];
#pragma unroll
            for (int j = 0; j < 8; ++j) {
                float y   = (acc[p][j] - mean) * inv * flw[j] + flb[j];
                float seq = (v[j] - mean2) * inv2 * lw[j] + lb[j];
                r[j] = fmaxf(y, 0.f) + seq;
            }
            float4 rlo = {r[0], r[1], r[2], r[3]};
            float4 rhi = {r[4], r[5], r[6], r[7]};
            *reinterpret_cast<float4*>(out + (long)n * Hd + hlo)      = rlo;
            *reinterpret_cast<float4*>(out + (long)n * Hd + hlo + 64) = rhi;
        }
    }
}

extern "C" void kernel_launch(void* const* d_in, const int* in_sizes, int n_in,
                              void* d_out, int out_size) {
    (void)in_sizes; (void)n_in; (void)out_size;
    const int*   input_ids  = (const int*)  d_in[0];
    const float* t_noise    = (const float*)d_in[1];
    const float* i_noise    = (const float*)d_in[2];
    const float* item_table = (const float*)d_in[3];
    const float* pos_table  = (const float*)d_in[4];
    const float* text_table = (const float*)d_in[5];
    const float* img_table  = (const float*)d_in[6];
    const float* fc_text_w  = (const float*)d_in[7];
    const float* fc_text_b  = (const float*)d_in[8];
    const float* fc_img_w   = (const float*)d_in[9];
    const float* fc_img_b   = (const float*)d_in[10];
    const float* ln_w       = (const float*)d_in[11];
    const float* ln_b       = (const float*)d_in[12];
    const float* mu_t_w     = (const float*)d_in[13];
    const float* mu_t_b     = (const float*)d_in[14];
    const float* sg_t_w     = (const float*)d_in[15];
    const float* sg_t_b     = (const float*)d_in[16];
    const float* mu_i_w     = (const float*)d_in[17];
    const float* mu_i_b     = (const float*)d_in[18];
    const float* sg_i_w     = (const float*)d_in[19];
    const float* sg_i_b     = (const float*)d_in[20];
    const float* gate_w     = (const float*)d_in[21];
    const float* gate_b     = (const float*)d_in[22];
    const float* texp_w     = (const float*)d_in[23];
    const float* texp_b     = (const float*)d_in[24];
    const float* iexp_w     = (const float*)d_in[25];
    const float* iexp_b     = (const float*)d_in[26];
    const float* fus_w      = (const float*)d_in[27];
    const float* fus_b      = (const float*)d_in[28];
    const float* fus_ln_w   = (const float*)d_in[29];
    const float* fus_ln_b   = (const float*)d_in[30];

    size_t smem = SMEM_FLOATS * sizeof(float);
    cudaFuncSetAttribute(sasrec_fused_kernel,
                         cudaFuncAttributeMaxDynamicSharedMemorySize, (int)smem);

    sasrec_fused_kernel<<<NTOK / TB, NTHREADS, smem>>>(
        input_ids, t_noise, i_noise, item_table, pos_table, text_table, img_table,
        fc_text_w, fc_text_b, fc_img_w, fc_img_b, ln_w, ln_b,
        mu_t_w, mu_t_b, sg_t_w, sg_t_b, mu_i_w, mu_i_b, sg_i_w, sg_i_b,
        gate_w, gate_b, texp_w, texp_b, iexp_w, iexp_b,
        fus_w, fus_b, fus_ln_w, fus_ln_b,
        (float*)d_out);
}

// round 7
// speedup vs baseline: 1.0135x; 1.0135x over previous
#include <cuda_runtime.h>
#include <math.h>

#define Hd      128
#define Ld      200
#define DTd     768
#define DId     512
#define Ed      8
#define NTOK    25600
#define TB      64
#define NTHREADS 256
#define KC      32
#define SWROW   128
#define SA      36
#define SX      132

#define OFF_W   0
#define OFF_A   4096
#define OFF_X   6400
#define OFF_Y   14848
#define OFF_GT  23296
#define OFF_GI  23808
#define OFF_IDS 24320
#define SMEM_FLOATS 24384

__device__ __forceinline__ float hreduce16(float v) {
    v += __shfl_xor_sync(0xffffffffu, v, 1);
    v += __shfl_xor_sync(0xffffffffu, v, 2);
    v += __shfl_xor_sync(0xffffffffu, v, 4);
    v += __shfl_xor_sync(0xffffffffu, v, 8);
    return v;
}

// ---- weight chunk: LDG half (prefetch) and swizzled STS half ----
__device__ __forceinline__ void w_ldg(const float* __restrict__ Wg, int ldw, int kc,
                                      int tid, float4 v[4]) {
#pragma unroll
    for (int j = 0; j < 4; ++j) {
        int idx = tid + j * NTHREADS;
        int h = idx >> 3, k4 = (idx & 7) * 4;
        v[j] = *reinterpret_cast<const float4*>(Wg + (long)h * ldw + kc + k4);
    }
}
__device__ __forceinline__ void w_sts(float* __restrict__ sW, int tid, const float4 v[4]) {
#pragma unroll
    for (int j = 0; j < 4; ++j) {
        int idx = tid + j * NTHREADS;
        int h = idx >> 3, k4 = (idx & 7) * 4;
        int m = (k4 >> 2) & 7;
        int fb = (((h >> 2) ^ m) << 2) + (h & 3);
        float* dst = sW + k4 * SWROW + fb;
        dst[0 * SWROW] = v[j].x;
        dst[1 * SWROW] = v[j].y;
        dst[2 * SWROW] = v[j].z;
        dst[3 * SWROW] = v[j].w;
    }
}
// ---- gathered activation chunk ----
__device__ __forceinline__ void ga_ldg(const float* __restrict__ T, int ldw, int kc,
                                       const int* __restrict__ sids, int tid, float4 v[2]) {
#pragma unroll
    for (int j = 0; j < 2; ++j) {
        int idx = tid + j * NTHREADS;
        int t = idx >> 3, kq = (idx & 7) * 4;
        v[j] = *reinterpret_cast<const float4*>(T + (long)sids[t] * ldw + kc + kq);
    }
}
__device__ __forceinline__ void ga_sts(float* __restrict__ sA, int tid, const float4 v[2]) {
#pragma unroll
    for (int j = 0; j < 2; ++j) {
        int idx = tid + j * NTHREADS;
        int t = idx >> 3, kq = (idx & 7) * 4;
        *reinterpret_cast<float4*>(sA + t * SA + kq) = v[j];
    }
}

__device__ __forceinline__ void gemm_chunk4(const float* __restrict__ a0,
                                            const float* __restrict__ a1,
                                            const float* __restrict__ a2,
                                            const float* __restrict__ a3,
                                            const float* __restrict__ sW,
                                            int tx, float acc[4][8]) {
#pragma unroll
    for (int k4 = 0; k4 < KC; k4 += 4) {
        const int m = (k4 >> 2) & 7;
        const float* wlo = sW + k4 * SWROW + ((tx ^ m) << 2);
        float4 A0 = *reinterpret_cast<const float4*>(a0 + k4);
        float4 A1 = *reinterpret_cast<const float4*>(a1 + k4);
        float4 A2 = *reinterpret_cast<const float4*>(a2 + k4);
        float4 A3 = *reinterpret_cast<const float4*>(a3 + k4);
        float av[4][4] = {{A0.x, A0.y, A0.z, A0.w}, {A1.x, A1.y, A1.z, A1.w},
                          {A2.x, A2.y, A2.z, A2.w}, {A3.x, A3.y, A3.z, A3.w}};
#pragma unroll
        for (int kk = 0; kk < 4; ++kk) {
            float4 b0 = *reinterpret_cast<const float4*>(wlo + kk * SWROW);
            float4 b1 = *reinterpret_cast<const float4*>(wlo + kk * SWROW + 64);
            float b[8] = {b0.x, b0.y, b0.z, b0.w, b1.x, b1.y, b1.z, b1.w};
#pragma unroll
            for (int p = 0; p < 4; ++p)
#pragma unroll
                for (int j = 0; j < 8; ++j)
                    acc[p][j] = fmaf(av[p][kk], b[j], acc[p][j]);
        }
    }
}

__device__ __forceinline__ void gemm_chunk2(const float* __restrict__ a0,
                                            const float* __restrict__ a1,
                                            const float* __restrict__ sW,
                                            int tx, float acc[2][8]) {
#pragma unroll
    for (int k4 = 0; k4 < KC; k4 += 4) {
        const int m = (k4 >> 2) & 7;
        const float* wlo = sW + k4 * SWROW + ((tx ^ m) << 2);
        float4 A0 = *reinterpret_cast<const float4*>(a0 + k4);
        float4 A1 = *reinterpret_cast<const float4*>(a1 + k4);
        float av[2][4] = {{A0.x, A0.y, A0.z, A0.w}, {A1.x, A1.y, A1.z, A1.w}};
#pragma unroll
        for (int kk = 0; kk < 4; ++kk) {
            float4 b0 = *reinterpret_cast<const float4*>(wlo + kk * SWROW);
            float4 b1 = *reinterpret_cast<const float4*>(wlo + kk * SWROW + 64);
            float b[8] = {b0.x, b0.y, b0.z, b0.w, b1.x, b1.y, b1.z, b1.w};
#pragma unroll
            for (int j = 0; j < 8; ++j) {
                acc[0][j] = fmaf(av[0][kk], b[j], acc[0][j]);
                acc[1][j] = fmaf(av[1][kk], b[j], acc[1][j]);
            }
        }
    }
}

__device__ __forceinline__ void gemm_gated(const float* __restrict__ a, float g,
                                           const float* __restrict__ sW,
                                           int tx, float acc[8]) {
#pragma unroll
    for (int k4 = 0; k4 < KC; k4 += 4) {
        const int m = (k4 >> 2) & 7;
        const float* wlo = sW + k4 * SWROW + ((tx ^ m) << 2);
        float4 A0 = *reinterpret_cast<const float4*>(a + k4);
        float av[4] = {A0.x * g, A0.y * g, A0.z * g, A0.w * g};
#pragma unroll
        for (int kk = 0; kk < 4; ++kk) {
            float4 b0 = *reinterpret_cast<const float4*>(wlo + kk * SWROW);
            float4 b1 = *reinterpret_cast<const float4*>(wlo + kk * SWROW + 64);
            acc[0] = fmaf(av[kk], b0.x, acc[0]);
            acc[1] = fmaf(av[kk], b0.y, acc[1]);
            acc[2] = fmaf(av[kk], b0.z, acc[2]);
            acc[3] = fmaf(av[kk], b0.w, acc[3]);
            acc[4] = fmaf(av[kk], b1.x, acc[4]);
            acc[5] = fmaf(av[kk], b1.y, acc[5]);
            acc[6] = fmaf(av[kk], b1.z, acc[6]);
            acc[7] = fmaf(av[kk], b1.w, acc[7]);
        }
    }
}

__device__ __forceinline__ void route8(float* g) {
    float m = g[0];
#pragma unroll
    for (int e = 1; e < Ed; ++e) m = fmaxf(m, g[e]);
    float ex[Ed]; float s = 0.f;
#pragma unroll
    for (int e = 0; e < Ed; ++e) { ex[e] = __expf(g[e] - m); s += ex[e]; }
    float inv = 1.f / s;
#pragma unroll
    for (int e = 0; e < Ed; ++e) ex[e] *= inv;
    int i1 = 0; float w1 = ex[0];
#pragma unroll
    for (int e = 1; e < Ed; ++e) if (ex[e] > w1) { w1 = ex[e]; i1 = e; }
    int i2 = -1; float w2 = -1.f;
#pragma unroll
    for (int e = 0; e < Ed; ++e) if (e != i1 && ex[e] > w2) { w2 = ex[e]; i2 = e; }
    float den = 1.f / (w1 + w2 + 1e-8f);
#pragma unroll
    for (int e = 0; e < Ed; ++e)
        g[e] = (e == i1) ? w1 * den : ((e == i2) ? w2 * den : 0.f);
}

__global__ __launch_bounds__(NTHREADS, 2)
void sasrec_fused_kernel(
    const int*   __restrict__ input_ids,
    const float* __restrict__ t_noise,   const float* __restrict__ i_noise,
    const float* __restrict__ item_table,const float* __restrict__ pos_table,
    const float* __restrict__ text_table,const float* __restrict__ img_table,
    const float* __restrict__ fc_text_w, const float* __restrict__ fc_text_b,
    const float* __restrict__ fc_img_w,  const float* __restrict__ fc_img_b,
    const float* __restrict__ ln_w,      const float* __restrict__ ln_b,
    const float* __restrict__ mu_t_w,    const float* __restrict__ mu_t_b,
    const float* __restrict__ sg_t_w,    const float* __restrict__ sg_t_b,
    const float* __restrict__ mu_i_w,    const float* __restrict__ mu_i_b,
    const float* __restrict__ sg_i_w,    const float* __restrict__ sg_i_b,
    const float* __restrict__ gate_w,    const float* __restrict__ gate_b,
    const float* __restrict__ texp_w,    const float* __restrict__ texp_b,
    const float* __restrict__ iexp_w,    const float* __restrict__ iexp_b,
    const float* __restrict__ fus_w,     const float* __restrict__ fus_b,
    const float* __restrict__ fus_ln_w,  const float* __restrict__ fus_ln_b,
    float*       __restrict__ out)
{
    extern __shared__ float sm[];
    float* sW  = sm + OFF_W;
    float* sA  = sm + OFF_A;
    float* sX  = sm + OFF_X;
    float* sY  = sm + OFF_Y;
    float* sgt = sm + OFF_GT;
    float* sgi = sm + OFF_GI;
    int*   sids = (int*)(sm + OFF_IDS);

    const int tid = threadIdx.x;
    const int tx  = tid & 15;
    const int ty  = tid >> 4;
    const int hlo = tx * 4;
    const int n0  = blockIdx.x * TB;

    if (tid < TB) sids[tid] = input_ids[n0 + tid];
    __syncthreads();

    float acc[4][8];
    float4 wv[4];
    float4 av[2];

    // ---------------- stage 1: text_emb -> sX ----------------
    {
#pragma unroll
        for (int p = 0; p < 4; ++p)
#pragma unroll
            for (int j = 0; j < 8; ++j) acc[p][j] = 0.f;
        w_ldg(fc_text_w, DTd, 0, tid, wv);
        ga_ldg(text_table, DTd, 0, sids, tid, av);
        for (int kc = 0; kc < DTd; kc += KC) {
            w_sts(sW, tid, wv);
            ga_sts(sA, tid, av);
            __syncthreads();
            if (kc + KC < DTd) {
                w_ldg(fc_text_w, DTd, kc + KC, tid, wv);
                ga_ldg(text_table, DTd, kc + KC, sids, tid, av);
            }
            gemm_chunk4(sA + ty * SA, sA + (ty + 16) * SA,
                        sA + (ty + 32) * SA, sA + (ty + 48) * SA, sW, tx, acc);
            __syncthreads();
        }
        float4 blo = *reinterpret_cast<const float4*>(fc_text_b + hlo);
        float4 bhi = *reinterpret_cast<const float4*>(fc_text_b + hlo + 64);
        float bb[8] = {blo.x, blo.y, blo.z, blo.w, bhi.x, bhi.y, bhi.z, bhi.w};
#pragma unroll
        for (int p = 0; p < 4; ++p) {
            int t = ty + 16 * p;
            float ss = 0.f;
#pragma unroll
            for (int j = 0; j < 8; ++j) { acc[p][j] += bb[j]; ss += acc[p][j] * acc[p][j]; }
            ss = hreduce16(ss);
            float sc = 1.f / fmaxf(sqrtf(ss), 1e-12f);
            float4 olo = {acc[p][0] * sc, acc[p][1] * sc, acc[p][2] * sc, acc[p][3] * sc};
            float4 ohi = {acc[p][4] * sc, acc[p][5] * sc, acc[p][6] * sc, acc[p][7] * sc};
            *reinterpret_cast<float4*>(sX + t * SX + hlo)      = olo;
            *reinterpret_cast<float4*>(sX + t * SX + hlo + 64) = ohi;
        }
    }

    // ---------------- stage 2: img_emb -> sY ----------------
    {
#pragma unroll
        for (int p = 0; p < 4; ++p)
#pragma unroll
            for (int j = 0; j < 8; ++j) acc[p][j] = 0.f;
        w_ldg(fc_img_w, DId, 0, tid, wv);
        ga_ldg(img_table, DId, 0, sids, tid, av);
        for (int kc = 0; kc < DId; kc += KC) {
            w_sts(sW, tid, wv);
            ga_sts(sA, tid, av);
            __syncthreads();
            if (kc + KC < DId) {
                w_ldg(fc_img_w, DId, kc + KC, tid, wv);
                ga_ldg(img_table, DId, kc + KC, sids, tid, av);
            }
            gemm_chunk4(sA + ty * SA, sA + (ty + 16) * SA,
                        sA + (ty + 32) * SA, sA + (ty + 48) * SA, sW, tx, acc);
            __syncthreads();
        }
        float4 blo = *reinterpret_cast<const float4*>(fc_img_b + hlo);
        float4 bhi = *reinterpret_cast<const float4*>(fc_img_b + hlo + 64);
        float bb[8] = {blo.x, blo.y, blo.z, blo.w, bhi.x, bhi.y, bhi.z, bhi.w};
#pragma unroll
        for (int p = 0; p < 4; ++p) {
            int t = ty + 16 * p;
            float ss = 0.f;
#pragma unroll
            for (int j = 0; j < 8; ++j) { acc[p][j] += bb[j]; ss += acc[p][j] * acc[p][j]; }
            ss = hreduce16(ss);
            float sc = 1.f / fmaxf(sqrtf(ss), 1e-12f);
            float4 olo = {acc[p][0] * sc, acc[p][1] * sc, acc[p][2] * sc, acc[p][3] * sc};
            float4 ohi = {acc[p][4] * sc, acc[p][5] * sc, acc[p][6] * sc, acc[p][7] * sc};
            *reinterpret_cast<float4*>(sY + t * SX + hlo)      = olo;
            *reinterpret_cast<float4*>(sY + t * SX + hlo + 64) = ohi;
        }
    }

    // ---------------- stages 3/4: VAE reparam (text then img) ----------------
#pragma unroll 1
    for (int mod = 0; mod < 2; ++mod) {
        float* sZ = mod ? sY : sX;
        const float* muW = mod ? mu_i_w : mu_t_w;
        const float* sgW = mod ? sg_i_w : sg_t_w;
        const float* muB = mod ? mu_i_b : mu_t_b;
        const float* sgB = mod ? sg_i_b : sg_t_b;
        const float* noi = mod ? i_noise : t_noise;
#pragma unroll 1
        for (int q = 0; q < 2; ++q) {
            const int tA = ty + 32 * q;
            float mu2[2][8], sg2[2][8];
#pragma unroll
            for (int p = 0; p < 2; ++p)
#pragma unroll
                for (int j = 0; j < 8; ++j) { mu2[p][j] = 0.f; sg2[p][j] = 0.f; }
            w_ldg(muW, Hd, 0, tid, wv);
            for (int kc = 0; kc < Hd; kc += KC) {
                w_sts(sW, tid, wv);
                __syncthreads();
                if (kc + KC < Hd) w_ldg(muW, Hd, kc + KC, tid, wv);
                else w_ldg(sgW, Hd, 0, tid, wv);
                gemm_chunk2(sZ + tA * SX + kc, sZ + (tA + 16) * SX + kc, sW, tx, mu2);
                __syncthreads();
            }
            for (int kc = 0; kc < Hd; kc += KC) {
                w_sts(sW, tid, wv);
                __syncthreads();
                if (kc + KC < Hd) w_ldg(sgW, Hd, kc + KC, tid, wv);
                gemm_chunk2(sZ + tA * SX + kc, sZ + (tA + 16) * SX + kc, sW, tx, sg2);
                __syncthreads();
            }
            float4 mblo = *reinterpret_cast<const float4*>(muB + hlo);
            float4 mbhi = *reinterpret_cast<const float4*>(muB + hlo + 64);
            float4 sblo = *reinterpret_cast<const float4*>(sgB + hlo);
            float4 sbhi = *reinterpret_cast<const float4*>(sgB + hlo + 64);
            float mb[8] = {mblo.x, mblo.y, mblo.z, mblo.w, mbhi.x, mbhi.y, mbhi.z, mbhi.w};
            float sb[8] = {sblo.x, sblo.y, sblo.z, sblo.w, sbhi.x, sbhi.y, sbhi.z, sbhi.w};
#pragma unroll
            for (int p = 0; p < 2; ++p) {
                int t = tA + 16 * p;
                const float* np = noi + (long)(n0 + t) * Hd;
                float4 nlo = *reinterpret_cast<const float4*>(np + hlo);
                float4 nhi = *reinterpret_cast<const float4*>(np + hlo + 64);
                float nn[8] = {nlo.x, nlo.y, nlo.z, nlo.w, nhi.x, nhi.y, nhi.z, nhi.w};
                float z[8];
#pragma unroll
                for (int j = 0; j < 8; ++j)
                    z[j] = mu2[p][j] + mb[j] + __expf(sg2[p][j] + sb[j]) * nn[j];
                float4 zlo = {z[0], z[1], z[2], z[3]};
                float4 zhi = {z[4], z[5], z[6], z[7]};
                *reinterpret_cast<float4*>(sZ + t * SX + hlo)      = zlo;
                *reinterpret_cast<float4*>(sZ + t * SX + hlo + 64) = zhi;
            }
        }
    }

    // ---------------- stage 5: gating ----------------
    __syncthreads();
    {
        int t  = tid >> 2;
        int e0 = (tid & 3) * 2;
#pragma unroll
        for (int qe = 0; qe < 2; ++qe) {
            int e = e0 + qe;
            const float* gw = gate_w + e * Hd;
            float dt = 0.f, di = 0.f;
#pragma unroll 8
            for (int k4 = 0; k4 < Hd; k4 += 4) {
                float4 w = *reinterpret_cast<const float4*>(gw + k4);
                float4 x = *reinterpret_cast<const float4*>(sX + t * SX + k4);
                float4 y = *reinterpret_cast<const float4*>(sY + t * SX + k4);
                dt = fmaf(x.x, w.x, fmaf(x.y, w.y, fmaf(x.z, w.z, fmaf(x.w, w.w, dt))));
                di = fmaf(y.x, w.x, fmaf(y.y, w.y, fmaf(y.z, w.z, fmaf(y.w, w.w, di))));
            }
            sgt[t * Ed + e] = dt + gate_b[e];
            sgi[t * Ed + e] = di + gate_b[e];
        }
    }
    __syncthreads();
    if (tid < TB) {
        route8(sgt + tid * Ed);
        route8(sgi + tid * Ed);
    }
    __syncthreads();

    // ---------------- stages 6/7: experts (top-2 sparse, prefetched) ----------------
#pragma unroll 1
    for (int mod = 0; mod < 2; ++mod) {
        float* sZ = mod ? sY : sX;
        const float* gates = mod ? sgi : sgt;
        const float* expW = mod ? iexp_w : texp_w;
        const float* expB = mod ? iexp_b : texp_b;
        float outv[4][8];
#pragma unroll
        for (int p = 0; p < 4; ++p) {
            int t = ty + 16 * p;
#pragma unroll
            for (int j = 0; j < 8; ++j) outv[p][j] = 0.f;
#pragma unroll
            for (int e = 0; e < Ed; ++e) {
                float g = gates[t * Ed + e];
                if (g != 0.f) {
                    const float* bp = expB + e * Hd;
                    float4 blo = *reinterpret_cast<const float4*>(bp + hlo);
                    float4 bhi = *reinterpret_cast<const float4*>(bp + hlo + 64);
                    float bb[8] = {blo.x, blo.y, blo.z, blo.w, bhi.x, bhi.y, bhi.z, bhi.w};
#pragma unroll
                    for (int j = 0; j < 8; ++j) outv[p][j] = fmaf(g, bb[j], outv[p][j]);
                }
            }
        }
        w_ldg(expW, Hd, 0, tid, wv);
#pragma unroll 1
        for (int e = 0; e < Ed; ++e) {
#pragma unroll 1
            for (int kc = 0; kc < Hd; kc += KC) {
                w_sts(sW, tid, wv);
                __syncthreads();
                {   // prefetch next (e,kc)
                    int nkc = kc + KC, ne = e;
                    if (nkc >= Hd) { nkc = 0; ne = e + 1; }
                    if (ne < Ed) w_ldg(expW + (long)ne * Hd * Hd, Hd, nkc, tid, wv);
                }
#pragma unroll
                for (int p = 0; p < 4; ++p) {
                    float g = gates[(ty + 16 * p) * Ed + e];
                    if (g != 0.f)
                        gemm_gated(sZ + (ty + 16 * p) * SX + kc, g, sW, tx, outv[p]);
                }
                __syncthreads();
            }
        }
#pragma unroll
        for (int p = 0; p < 4; ++p) {
            int t = ty + 16 * p;
            float4 olo = {outv[p][0], outv[p][1], outv[p][2], outv[p][3]};
            float4 ohi = {outv[p][4], outv[p][5], outv[p][6], outv[p][7]};
            *reinterpret_cast<float4*>(sZ + t * SX + hlo)      = olo;
            *reinterpret_cast<float4*>(sZ + t * SX + hlo + 64) = ohi;
        }
        __syncthreads();
    }

    // ---------------- stage 8: fusion + recomputed seq_emb ----------------
    {
#pragma unroll
        for (int p = 0; p < 4; ++p)
#pragma unroll
            for (int j = 0; j < 8; ++j) acc[p][j] = 0.f;
        w_ldg(fus_w, 2 * Hd, 0, tid, wv);
        for (int kc = 0; kc < 2 * Hd; kc += KC) {
            w_sts(sW, tid, wv);
            __syncthreads();
            if (kc + KC < 2 * Hd) w_ldg(fus_w, 2 * Hd, kc + KC, tid, wv);
            const float* base = (kc < Hd) ? sX : sY;
            int ko = (kc < Hd) ? kc : (kc - Hd);
            gemm_chunk4(base + ty * SX + ko, base + (ty + 16) * SX + ko,
                        base + (ty + 32) * SX + ko, base + (ty + 48) * SX + ko,
                        sW, tx, acc);
            __syncthreads();
        }
        float4 fblo = *reinterpret_cast<const float4*>(fus_b + hlo);
        float4 fbhi = *reinterpret_cast<const float4*>(fus_b + hlo + 64);
        float fb[8] = {fblo.x, fblo.y, fblo.z, fblo.w, fbhi.x, fbhi.y, fbhi.z, fbhi.w};
        float4 fwlo = *reinterpret_cast<const float4*>(fus_ln_w + hlo);
        float4 fwhi = *reinterpret_cast<const float4*>(fus_ln_w + hlo + 64);
        float flw[8] = {fwlo.x, fwlo.y, fwlo.z, fwlo.w, fwhi.x, fwhi.y, fwhi.z, fwhi.w};
        float4 fllo = *reinterpret_cast<const float4*>(fus_ln_b + hlo);
        float4 flhi = *reinterpret_cast<const float4*>(fus_ln_b + hlo + 64);
        float flb[8] = {fllo.x, fllo.y, fllo.z, fllo.w, flhi.x, flhi.y, flhi.z, flhi.w};
        float4 lwlo = *reinterpret_cast<const float4*>(ln_w + hlo);
        float4 lwhi = *reinterpret_cast<const float4*>(ln_w + hlo + 64);
        float lw[8] = {lwlo.x, lwlo.y, lwlo.z, lwlo.w, lwhi.x, lwhi.y, lwhi.z, lwhi.w};
        float4 lblo = *reinterpret_cast<const float4*>(ln_b + hlo);
        float4 lbhi = *reinterpret_cast<const float4*>(ln_b + hlo + 64);
        float lb[8] = {lblo.x, lblo.y, lblo.z, lblo.w, lbhi.x, lbhi.y, lbhi.z, lbhi.w};
#pragma unroll
        for (int p = 0; p < 4; ++p) {
            int t = ty + 16 * p;
            int n = n0 + t;
            float s = 0.f, sq = 0.f;
#pragma unroll
            for (int j = 0; j < 8; ++j) {
                acc[p][j] += fb[j];
                s += acc[p][j]; sq += acc[p][j] * acc[p][j];
            }
            s  = hreduce16(s);
            sq = hreduce16(sq);
            float mean = s * (1.f / Hd);
            float var  = sq * (1.f / Hd) - mean * mean;
            float inv  = rsqrtf(var + 1e-5f);
            int id  = sids[t];
            int pos = n % Ld;
            const float* ip = item_table + (long)id * Hd;
            const float* pp = pos_table + pos * Hd;
            float4 ilo = *reinterpret_cast<const float4*>(ip + hlo);
            float4 ihi = *reinterpret_cast<const float4*>(ip + hlo + 64);
            float4 plo = *reinterpret_cast<const float4*>(pp + hlo);
            float4 phi = *reinterpret_cast<const float4*>(pp + hlo + 64);
            float v[8] = {ilo.x + plo.x, ilo.y + plo.y, ilo.z + plo.z, ilo.w + plo.w,
                          ihi.x + phi.x, ihi.y + phi.y, ihi.z + phi.z, ihi.w + phi.w};
            float s2 = 0.f, sq2 = 0.f;
#pragma unroll
            for (int j = 0; j < 8; ++j) { s2 += v[j]; sq2 += v[j] * v[j]; }
            s2  = hreduce16(s2);
            sq2 = hreduce16(sq2);
            float mean2 = s2 * (1.f / Hd);
            float var2  = sq2 * (1.f / Hd) - mean2 * mean2;
            float inv2  = rsqrtf(var2 + 1e-12f);
            float r[8];
#pragma unroll
            for (int j = 0; j < 8; ++j) {
                float y   = (acc[p][j] - mean) * inv * flw[j] + flb[j];
                float seq = (v[j] - mean2) * inv2 * lw[j] + lb[j];
                r[j] = fmaxf(y, 0.f) + seq;
            }
            float4 rlo = {r[0], r[1], r[2], r[3]};
            float4 rhi = {r[4], r[5], r[6], r[7]};
            *reinterpret_cast<float4*>(out + (long)n * Hd + hlo)      = rlo;
            *reinterpret_cast<float4*>(out + (long)n * Hd + hlo + 64) = rhi;
        }
    }
}

extern "C" void kernel_launch(void* const* d_in, const int* in_sizes, int n_in,
                              void* d_out, int out_size) {
    (void)in_sizes; (void)n_in; (void)out_size;
    const int*   input_ids  = (const int*)  d_in[0];
    const float* t_noise    = (const float*)d_in[1];
    const float* i_noise    = (const float*)d_in[2];
    const float* item_table = (const float*)d_in[3];
    const float* pos_table  = (const float*)d_in[4];
    const float* text_table = (const float*)d_in[5];
    const float* img_table  = (const float*)d_in[6];
    const float* fc_text_w  = (const float*)d_in[7];
    const float* fc_text_b  = (const float*)d_in[8];
    const float* fc_img_w   = (const float*)d_in[9];
    const float* fc_img_b   = (const float*)d_in[10];
    const float* ln_w       = (const float*)d_in[11];
    const float* ln_b       = (const float*)d_in[12];
    const float* mu_t_w     = (const float*)d_in[13];
    const float* mu_t_b     = (const float*)d_in[14];
    const float* sg_t_w     = (const float*)d_in[15];
    const float* sg_t_b     = (const float*)d_in[16];
    const float* mu_i_w     = (const float*)d_in[17];
    const float* mu_i_b     = (const float*)d_in[18];
    const float* sg_i_w     = (const float*)d_in[19];
    const float* sg_i_b     = (const float*)d_in[20];
    const float* gate_w     = (const float*)d_in[21];
    const float* gate_b     = (const float*)d_in[22];
    const float* texp_w     = (const float*)d_in[23];
    const float* texp_b     = (const float*)d_in[24];
    const float* iexp_w     = (const float*)d_in[25];
    const float* iexp_b     = (const float*)d_in[26];
    const float* fus_w      = (const float*)d_in[27];
    const float* fus_b      = (const float*)d_in[28];
    const float* fus_ln_w   = (const float*)d_in[29];
    const float* fus_ln_b   = (const float*)d_in[30];

    size_t smem = SMEM_FLOATS * sizeof(float);
    cudaFuncSetAttribute(sasrec_fused_kernel,
                         cudaFuncAttributeMaxDynamicSharedMemorySize, (int)smem);

    sasrec_fused_kernel<<<NTOK / TB, NTHREADS, smem>>>(
        input_ids, t_noise, i_noise, item_table, pos_table, text_table, img_table,
        fc_text_w, fc_text_b, fc_img_w, fc_img_b, ln_w, ln_b,
        mu_t_w, mu_t_b, sg_t_w, sg_t_b, mu_i_w, mu_i_b, sg_i_w, sg_i_b,
        gate_w, gate_b, texp_w, texp_b, iexp_w, iexp_b,
        fus_w, fus_b, fus_ln_w, fus_ln_b,
        (float*)d_out);
}

// round 8
// speedup vs baseline: 1.8102x; 1.7860x over previous
#include <cuda_runtime.h>
#include <math.h>
#include <stdint.h>

#define Hd 128
#define Ld 200
#define DTd 768
#define DId 512
#define NTOK 25600
#define TB 64
#define NTH 256

// smem layout in u32 units
#define O_WH 0
#define O_WL 2560
#define O_AH 8448
#define O_AL 9728
#define O_XH 11008
#define O_XL 15360
#define O_YH 19712
#define O_YL 24064
#define O_GT 28416
#define O_GI 28928
#define O_ID 29440
#define SMEMU 29504   // 118016 bytes, 1 CTA/SM (opt-in)

__device__ __forceinline__ uint32_t cvt2(float lo, float hi) {
    uint32_t r;
    asm("cvt.rn.bf16x2.f32 %0, %1, %2;" : "=r"(r) : "f"(hi), "f"(lo));
    return r;
}
__device__ __forceinline__ float blo(uint32_t u) { return __uint_as_float(u << 16); }
__device__ __forceinline__ float bhi(uint32_t u) { return __uint_as_float(u & 0xffff0000u); }

__device__ __forceinline__ void splitq(float4 a, float4 b, uint4& h, uint4& l) {
    h.x = cvt2(a.x, a.y); l.x = cvt2(a.x - blo(h.x), a.y - bhi(h.x));
    h.y = cvt2(a.z, a.w); l.y = cvt2(a.z - blo(h.y), a.w - bhi(h.y));
    h.z = cvt2(b.x, b.y); l.z = cvt2(b.x - blo(h.z), b.y - bhi(h.z));
    h.w = cvt2(b.z, b.w); l.w = cvt2(b.z - blo(h.w), b.w - bhi(h.w));
}

__device__ __forceinline__ void MMA(float* d, uint32_t a0, uint32_t a1, uint32_t a2, uint32_t a3,
                                    uint32_t b0, uint32_t b1) {
    asm volatile("mma.sync.aligned.m16n8k16.row.col.f32.bf16.bf16.f32 "
                 "{%0,%1,%2,%3},{%4,%5,%6,%7},{%8,%9},{%0,%1,%2,%3};"
                 : "+f"(d[0]), "+f"(d[1]), "+f"(d[2]), "+f"(d[3])
                 : "r"(a0), "r"(a1), "r"(a2), "r"(a3), "r"(b0), "r"(b1));
}

__device__ __forceinline__ void zeroD(float D[8][4]) {
#pragma unroll
    for (int n = 0; n < 8; ++n)
#pragma unroll
        for (int j = 0; j < 4; ++j) D[n][j] = 0.f;
}

// ---- weight chunk 128h x 32k: prefetch fp32, convert+store as split bf16x2 [h][kpair] stride 20
__device__ __forceinline__ void w_ldg(const float* __restrict__ W, int ldw, int kc,
                                      int tid, float4 v[4]) {
#pragma unroll
    for (int j = 0; j < 2; ++j) {
        int idx = tid + j * NTH;
        int h = idx >> 2, q = idx & 3;
        const float* p = W + (long)h * ldw + kc + q * 8;
        v[2 * j]     = *(const float4*)p;
        v[2 * j + 1] = *(const float4*)(p + 4);
    }
}
__device__ __forceinline__ void w_sts(uint32_t* sWh, uint32_t* sWl, int tid, const float4 v[4]) {
#pragma unroll
    for (int j = 0; j < 2; ++j) {
        int idx = tid + j * NTH;
        int h = idx >> 2, q = idx & 3;
        uint4 hi, lo;
        splitq(v[2 * j], v[2 * j + 1], hi, lo);
        *(uint4*)(sWh + h * 20 + q * 4) = hi;
        *(uint4*)(sWl + h * 20 + q * 4) = lo;
    }
}
// ---- gathered activation chunk 64tok x 32k -> [tok][kpair] stride 20
__device__ __forceinline__ void ga_ldg(const float* __restrict__ T, int ldw, int kc,
                                       const int* sids, int tid, float4 v[2]) {
    int tok = tid >> 2, q = tid & 3;
    const float* p = T + (long)sids[tok] * ldw + kc + q * 8;
    v[0] = *(const float4*)p;
    v[1] = *(const float4*)(p + 4);
}
__device__ __forceinline__ void ga_sts(uint32_t* sAh, uint32_t* sAl, int tid, const float4 v[2]) {
    int tok = tid >> 2, q = tid & 3;
    uint4 hi, lo;
    splitq(v[0], v[1], hi, lo);
    *(uint4*)(sAh + tok * 20 + q * 4) = hi;
    *(uint4*)(sAl + tok * 20 + q * 4) = lo;
}

// ---- one KC=32 chunk of 3-term mma: warp tile 16h x 64tok
__device__ __forceinline__ void mma_chunk(const uint32_t* __restrict__ Wh, const uint32_t* __restrict__ Wl,
                                          const uint32_t* __restrict__ Bh, const uint32_t* __restrict__ Bl,
                                          int bst, int lane, float D[8][4]) {
    int g = lane >> 2, q = lane & 3;
#pragma unroll
    for (int kt = 0; kt < 2; ++kt) {
        int o = kt * 8 + q;
        uint32_t ah0 = Wh[g * 20 + o], ah1 = Wh[(g + 8) * 20 + o];
        uint32_t ah2 = Wh[g * 20 + o + 4], ah3 = Wh[(g + 8) * 20 + o + 4];
        uint32_t al0 = Wl[g * 20 + o], al1 = Wl[(g + 8) * 20 + o];
        uint32_t al2 = Wl[g * 20 + o + 4], al3 = Wl[(g + 8) * 20 + o + 4];
#pragma unroll
        for (int nt = 0; nt < 8; ++nt) {
            const uint32_t* bp = Bh + (nt * 8 + g) * bst + o;
            const uint32_t* bq = Bl + (nt * 8 + g) * bst + o;
            uint32_t b0 = bp[0], b1 = bp[4];
            uint32_t c0 = bq[0], c1 = bq[4];
            MMA(D[nt], ah0, ah1, ah2, ah3, b0, b1);
            MMA(D[nt], ah0, ah1, ah2, ah3, c0, c1);
            MMA(D[nt], al0, al1, al2, al3, b0, b1);
        }
    }
}

// ---- stage D fragments to fp32 [tok][h] stride 132
__device__ __forceinline__ void stage_D(float* sWf, float D[8][4], int lane, int hb) {
    int g = lane >> 2, q = lane & 3;
#pragma unroll
    for (int nt = 0; nt < 8; ++nt) {
        int t0 = nt * 8 + 2 * q;
        float* p0 = sWf + t0 * 132 + hb + g;
        float* p1 = sWf + (t0 + 1) * 132 + hb + g;
        p0[0] = D[nt][0]; p1[0] = D[nt][1]; p0[8] = D[nt][2]; p1[8] = D[nt][3];
    }
}

__device__ __forceinline__ void route8(float* g) {
    float m = g[0];
#pragma unroll
    for (int e = 1; e < 8; ++e) m = fmaxf(m, g[e]);
    float ex[8]; float s = 0.f;
#pragma unroll
    for (int e = 0; e < 8; ++e) { ex[e] = __expf(g[e] - m); s += ex[e]; }
    float inv = 1.f / s;
#pragma unroll
    for (int e = 0; e < 8; ++e) ex[e] *= inv;
    int i1 = 0; float w1 = ex[0];
#pragma unroll
    for (int e = 1; e < 8; ++e) if (ex[e] > w1) { w1 = ex[e]; i1 = e; }
    int i2 = -1; float w2 = -1.f;
#pragma unroll
    for (int e = 0; e < 8; ++e) if (e != i1 && ex[e] > w2) { w2 = ex[e]; i2 = e; }
    float den = 1.f / (w1 + w2 + 1e-8f);
#pragma unroll
    for (int e = 0; e < 8; ++e)
        g[e] = (e == i1) ? w1 * den : ((e == i2) ? w2 * den : 0.f);
}

__global__ __launch_bounds__(NTH, 1)
void sasrec_mma_kernel(
    const int*   __restrict__ input_ids,
    const float* __restrict__ t_noise,   const float* __restrict__ i_noise,
    const float* __restrict__ item_table,const float* __restrict__ pos_table,
    const float* __restrict__ text_table,const float* __restrict__ img_table,
    const float* __restrict__ fc_text_w, const float* __restrict__ fc_text_b,
    const float* __restrict__ fc_img_w,  const float* __restrict__ fc_img_b,
    const float* __restrict__ ln_w,      const float* __restrict__ ln_b,
    const float* __restrict__ mu_t_w,    const float* __restrict__ mu_t_b,
    const float* __restrict__ sg_t_w,    const float* __restrict__ sg_t_b,
    const float* __restrict__ mu_i_w,    const float* __restrict__ mu_i_b,
    const float* __restrict__ sg_i_w,    const float* __restrict__ sg_i_b,
    const float* __restrict__ gate_w,    const float* __restrict__ gate_b,
    const float* __restrict__ texp_w,    const float* __restrict__ texp_b,
    const float* __restrict__ iexp_w,    const float* __restrict__ iexp_b,
    const float* __restrict__ fus_w,     const float* __restrict__ fus_b,
    const float* __restrict__ fus_ln_w,  const float* __restrict__ fus_ln_b,
    float*       __restrict__ out)
{
    extern __shared__ uint32_t su[];
    float*    sWf = (float*)su;
    uint32_t *sWh = su + O_WH, *sWl = su + O_WL;
    uint32_t *sAh = su + O_AH, *sAl = su + O_AL;
    uint32_t *sXh = su + O_XH, *sXl = su + O_XL;
    uint32_t *sYh = su + O_YH, *sYl = su + O_YL;
    float *sgt = (float*)(su + O_GT), *sgi = (float*)(su + O_GI);
    int* sids = (int*)(su + O_ID);

    const int tid = threadIdx.x, lane = tid & 31, wid = tid >> 5;
    const int hb = wid * 16;
    const int n0 = blockIdx.x * TB;
    const int tok = tid >> 2, pq = tid & 3;   // epilogue layout: 4 threads/token, 32 h each

    if (tid < TB) sids[tid] = input_ids[n0 + tid];
    __syncthreads();

    float D[8][4];
    float4 wv[4], av[2];

    // ============ stages 1-2: modality embeddings (l2norm(table@W^T + b)) ============
#pragma unroll 1
    for (int mod = 0; mod < 2; ++mod) {
        const float* tbl = mod ? img_table : text_table;
        const float* Wg  = mod ? fc_img_w : fc_text_w;
        const float* Bb  = mod ? fc_img_b : fc_text_b;
        const int Kd = mod ? DId : DTd;
        uint32_t* szh = mod ? sYh : sXh;
        uint32_t* szl = mod ? sYl : sXl;
        zeroD(D);
        w_ldg(Wg, Kd, 0, tid, wv);
        ga_ldg(tbl, Kd, 0, sids, tid, av);
        const int nck = Kd / 32;
        for (int c = 0; c < nck; ++c) {
            w_sts(sWh, sWl, tid, wv);
            ga_sts(sAh, sAl, tid, av);
            __syncthreads();
            if (c + 1 < nck) {
                w_ldg(Wg, Kd, (c + 1) * 32, tid, wv);
                ga_ldg(tbl, Kd, (c + 1) * 32, sids, tid, av);
            }
            mma_chunk(sWh + hb * 20, sWl + hb * 20, sAh, sAl, 20, lane, D);
            __syncthreads();
        }
        stage_D(sWf, D, lane, hb);
        __syncthreads();
        {   // epilogue: bias + l2norm + pack
            float v[32]; float ss = 0.f;
#pragma unroll
            for (int j = 0; j < 8; ++j) {
                float4 a = *(const float4*)(sWf + tok * 132 + pq * 32 + j * 4);
                float4 b = *(const float4*)(Bb + pq * 32 + j * 4);
                v[j*4+0] = a.x + b.x; v[j*4+1] = a.y + b.y;
                v[j*4+2] = a.z + b.z; v[j*4+3] = a.w + b.w;
#pragma unroll
                for (int k = 0; k < 4; ++k) ss += v[j*4+k] * v[j*4+k];
            }
            ss += __shfl_xor_sync(0xffffffffu, ss, 1);
            ss += __shfl_xor_sync(0xffffffffu, ss, 2);
            float sc = 1.f / fmaxf(sqrtf(ss), 1e-12f);
#pragma unroll
            for (int j = 0; j < 32; ++j) v[j] *= sc;
#pragma unroll
            for (int j = 0; j < 4; ++j) {
                uint4 hi, lo;
                splitq(*(const float4*)(v + j * 8), *(const float4*)(v + j * 8 + 4), hi, lo);
                *(uint4*)(szh + tok * 68 + pq * 16 + j * 4) = hi;
                *(uint4*)(szl + tok * 68 + pq * 16 + j * 4) = lo;
            }
        }
        __syncthreads();
    }

    // ============ stages 3-4: VAE reparam (mu staged via out-global scratch) ============
#pragma unroll 1
    for (int mod = 0; mod < 2; ++mod) {
        const float* muW = mod ? mu_i_w : mu_t_w;
        const float* sgW = mod ? sg_i_w : sg_t_w;
        const float* muB = mod ? mu_i_b : mu_t_b;
        const float* sgB = mod ? sg_i_b : sg_t_b;
        const float* noi = mod ? i_noise : t_noise;
        uint32_t* szh = mod ? sYh : sXh;
        uint32_t* szl = mod ? sYl : sXl;
        // mu GEMM
        zeroD(D);
        w_ldg(muW, Hd, 0, tid, wv);
        for (int c = 0; c < 4; ++c) {
            w_sts(sWh, sWl, tid, wv);
            __syncthreads();
            if (c < 3) w_ldg(muW, Hd, (c + 1) * 32, tid, wv);
            else       w_ldg(sgW, Hd, 0, tid, wv);
            mma_chunk(sWh + hb * 20, sWl + hb * 20, szh + c * 16, szl + c * 16, 68, lane, D);
            __syncthreads();
        }
        stage_D(sWf, D, lane, hb);
        __syncthreads();
        // spill mu rows to out (scratch; overwritten by fusion later)
#pragma unroll
        for (int j = 0; j < 4; ++j) {
            int idx = tid + j * NTH;          // 1024 items of 8 floats
            int t = idx >> 4, q = idx & 15;
            float4 a = *(const float4*)(sWf + t * 132 + q * 8);
            float4 b = *(const float4*)(sWf + t * 132 + q * 8 + 4);
            float* p = out + (long)(n0 + t) * Hd + q * 8;
            *(float4*)p = a; *(float4*)(p + 4) = b;
        }
        __syncthreads();
        // sg GEMM
        zeroD(D);
        for (int c = 0; c < 4; ++c) {
            w_sts(sWh, sWl, tid, wv);
            __syncthreads();
            if (c < 3) w_ldg(sgW, Hd, (c + 1) * 32, tid, wv);
            mma_chunk(sWh + hb * 20, sWl + hb * 20, szh + c * 16, szl + c * 16, 68, lane, D);
            __syncthreads();
        }
        stage_D(sWf, D, lane, hb);
        __syncthreads();
        {   // epilogue: z = mu + mb + exp(sg+sb)*noise, pack into szh/szl
            long n = n0 + tok;
#pragma unroll
            for (int j = 0; j < 4; ++j) {
                int o = pq * 32 + j * 8;
                float z[8];
#pragma unroll
                for (int k = 0; k < 8; ++k) {
                    float sg = sWf[tok * 132 + o + k];
                    float mu = out[n * Hd + o + k];
                    z[k] = mu + muB[o + k] + __expf(sg + sgB[o + k]) * noi[n * Hd + o + k];
                }
                uint4 hi, lo;
                splitq(*(const float4*)z, *(const float4*)(z + 4), hi, lo);
                *(uint4*)(szh + tok * 68 + pq * 16 + j * 4) = hi;
                *(uint4*)(szl + tok * 68 + pq * 16 + j * 4) = lo;
            }
        }
        __syncthreads();
    }

    // ============ stage 5: gating ============
    {
        int t = tok, e0 = pq * 2;
        float d0t = 0.f, d0i = 0.f, d1t = 0.f, d1i = 0.f;
        const uint32_t *xh = sXh + t * 68, *xl = sXl + t * 68;
        const uint32_t *yh = sYh + t * 68, *yl = sYl + t * 68;
#pragma unroll 4
        for (int k8 = 0; k8 < 16; ++k8) {
            float zx[8], zy[8];
#pragma unroll
            for (int j = 0; j < 4; ++j) {
                uint32_t a = xh[k8 * 4 + j], b = xl[k8 * 4 + j];
                zx[2*j] = blo(a) + blo(b); zx[2*j+1] = bhi(a) + bhi(b);
                a = yh[k8 * 4 + j]; b = yl[k8 * 4 + j];
                zy[2*j] = blo(a) + blo(b); zy[2*j+1] = bhi(a) + bhi(b);
            }
#pragma unroll
            for (int qe = 0; qe < 2; ++qe) {
                const float* gw = gate_w + (e0 + qe) * Hd + k8 * 8;
                float4 w1 = *(const float4*)gw, w2 = *(const float4*)(gw + 4);
                float wa[8] = {w1.x, w1.y, w1.z, w1.w, w2.x, w2.y, w2.z, w2.w};
                float st = 0.f, si = 0.f;
#pragma unroll
                for (int k = 0; k < 8; ++k) { st += zx[k] * wa[k]; si += zy[k] * wa[k]; }
                if (qe == 0) { d0t += st; d0i += si; } else { d1t += st; d1i += si; }
            }
        }
        sgt[t * 8 + e0]     = d0t + gate_b[e0];
        sgt[t * 8 + e0 + 1] = d1t + gate_b[e0 + 1];
        sgi[t * 8 + e0]     = d0i + gate_b[e0];
        sgi[t * 8 + e0 + 1] = d1i + gate_b[e0 + 1];
    }
    __syncthreads();
    if (tid < TB) { route8(sgt + tid * 8); route8(sgi + tid * 8); }
    __syncthreads();

    // ============ stages 6-7: dense experts, gate folded in fp32 regs ============
#pragma unroll 1
    for (int mod = 0; mod < 2; ++mod) {
        const float* eW = mod ? iexp_w : texp_w;
        const float* eB = mod ? iexp_b : texp_b;
        const float* gs = mod ? sgi : sgt;
        uint32_t* szh = mod ? sYh : sXh;
        uint32_t* szl = mod ? sYl : sXl;
        float acc[8][4];
        zeroD(acc); zeroD(D);
        w_ldg(eW, Hd, 0, tid, wv);
#pragma unroll 1
        for (int e = 0; e < 8; ++e) {
#pragma unroll 1
            for (int c = 0; c < 4; ++c) {
                w_sts(sWh, sWl, tid, wv);
                __syncthreads();
                if (!(e == 7 && c == 3)) {
                    const float* nw = (c < 3) ? eW + (long)e * Hd * Hd : eW + (long)(e + 1) * Hd * Hd;
                    w_ldg(nw, Hd, (c < 3) ? (c + 1) * 32 : 0, tid, wv);
                }
                mma_chunk(sWh + hb * 20, sWl + hb * 20, szh + c * 16, szl + c * 16, 68, lane, D);
                __syncthreads();
            }
            int g = lane >> 2, q = lane & 3;
            float b0 = eB[e * Hd + hb + g], b1 = eB[e * Hd + hb + g + 8];
#pragma unroll
            for (int nt = 0; nt < 8; ++nt) {
                int t0 = nt * 8 + 2 * q;
                float g0 = gs[t0 * 8 + e], g1 = gs[(t0 + 1) * 8 + e];
                acc[nt][0] += g0 * (D[nt][0] + b0);
                acc[nt][1] += g1 * (D[nt][1] + b0);
                acc[nt][2] += g0 * (D[nt][2] + b1);
                acc[nt][3] += g1 * (D[nt][3] + b1);
                D[nt][0] = D[nt][1] = D[nt][2] = D[nt][3] = 0.f;
            }
        }
        stage_D(sWf, acc, lane, hb);
        __syncthreads();
#pragma unroll
        for (int j = 0; j < 4; ++j) {
            uint4 hi, lo;
            splitq(*(const float4*)(sWf + tok * 132 + pq * 32 + j * 8),
                   *(const float4*)(sWf + tok * 132 + pq * 32 + j * 8 + 4), hi, lo);
            *(uint4*)(szh + tok * 68 + pq * 16 + j * 4) = hi;
            *(uint4*)(szl + tok * 68 + pq * 16 + j * 4) = lo;
        }
        __syncthreads();
    }

    // ============ stage 8: fusion (K=256 over X then Y) + LN/relu + seq_emb ============
    zeroD(D);
    w_ldg(fus_w, 2 * Hd, 0, tid, wv);
    for (int c = 0; c < 8; ++c) {
        w_sts(sWh, sWl, tid, wv);
        __syncthreads();
        if (c < 7) w_ldg(fus_w, 2 * Hd, (c + 1) * 32, tid, wv);
        const uint32_t* Bh = (c < 4) ? sXh + c * 16 : sYh + (c - 4) * 16;
        const uint32_t* Bl = (c < 4) ? sXl + c * 16 : sYl + (c - 4) * 16;
        mma_chunk(sWh + hb * 20, sWl + hb * 20, Bh, Bl, 68, lane, D);
        __syncthreads();
    }
    stage_D(sWf, D, lane, hb);
    __syncthreads();
    {
        long n = n0 + tok;
        float v[32]; float s = 0.f, s2 = 0.f;
#pragma unroll
        for (int j = 0; j < 8; ++j) {
            float4 a = *(const float4*)(sWf + tok * 132 + pq * 32 + j * 4);
            float4 b = *(const float4*)(fus_b + pq * 32 + j * 4);
            v[j*4+0] = a.x + b.x; v[j*4+1] = a.y + b.y;
            v[j*4+2] = a.z + b.z; v[j*4+3] = a.w + b.w;
#pragma unroll
            for (int k = 0; k < 4; ++k) { s += v[j*4+k]; s2 += v[j*4+k] * v[j*4+k]; }
        }
        s  += __shfl_xor_sync(0xffffffffu, s, 1);  s  += __shfl_xor_sync(0xffffffffu, s, 2);
        s2 += __shfl_xor_sync(0xffffffffu, s2, 1); s2 += __shfl_xor_sync(0xffffffffu, s2, 2);
        float mean = s * (1.f / Hd);
        float var  = s2 * (1.f / Hd) - mean * mean;
        float inv  = rsqrtf(var + 1e-5f);
        int id = sids[tok], pos = (int)(n % Ld);
        float w[32]; float t1 = 0.f, t2 = 0.f;
#pragma unroll
        for (int j = 0; j < 8; ++j) {
            float4 a = *(const float4*)(item_table + (long)id * Hd + pq * 32 + j * 4);
            float4 b = *(const float4*)(pos_table + pos * Hd + pq * 32 + j * 4);
            w[j*4+0] = a.x + b.x; w[j*4+1] = a.y + b.y;
            w[j*4+2] = a.z + b.z; w[j*4+3] = a.w + b.w;
#pragma unroll
            for (int k = 0; k < 4; ++k) { t1 += w[j*4+k]; t2 += w[j*4+k] * w[j*4+k]; }
        }
        t1 += __shfl_xor_sync(0xffffffffu, t1, 1); t1 += __shfl_xor_sync(0xffffffffu, t1, 2);
        t2 += __shfl_xor_sync(0xffffffffu, t2, 1); t2 += __shfl_xor_sync(0xffffffffu, t2, 2);
        float mean2 = t1 * (1.f / Hd);
        float var2  = t2 * (1.f / Hd) - mean2 * mean2;
        float inv2  = rsqrtf(var2 + 1e-12f);
#pragma unroll
        for (int j = 0; j < 8; ++j) {
            int o = pq * 32 + j * 4;
            float4 lw  = *(const float4*)(fus_ln_w + o);
            float4 lb  = *(const float4*)(fus_ln_b + o);
            float4 slw = *(const float4*)(ln_w + o);
            float4 slb = *(const float4*)(ln_b + o);
            float4 r;
            r.x = fmaxf((v[j*4+0] - mean) * inv * lw.x + lb.x, 0.f) + (w[j*4+0] - mean2) * inv2 * slw.x + slb.x;
            r.y = fmaxf((v[j*4+1] - mean) * inv * lw.y + lb.y, 0.f) + (w[j*4+1] - mean2) * inv2 * slw.y + slb.y;
            r.z = fmaxf((v[j*4+2] - mean) * inv * lw.z + lb.z, 0.f) + (w[j*4+2] - mean2) * inv2 * slw.z + slb.z;
            r.w = fmaxf((v[j*4+3] - mean) * inv * lw.w + lb.w, 0.f) + (w[j*4+3] - mean2) * inv2 * slw.w + slb.w;
            *(float4*)(out + n * Hd + o) = r;
        }
    }
}

extern "C" void kernel_launch(void* const* d_in, const int* in_sizes, int n_in,
                              void* d_out, int out_size) {
    (void)in_sizes; (void)n_in; (void)out_size;
    size_t smem = SMEMU * sizeof(uint32_t);
    cudaFuncSetAttribute(sasrec_mma_kernel,
                         cudaFuncAttributeMaxDynamicSharedMemorySize, (int)smem);
    sasrec_mma_kernel<<<NTOK / TB, NTH, smem>>>(
        (const int*)d_in[0], (const float*)d_in[1], (const float*)d_in[2],
        (const float*)d_in[3], (const float*)d_in[4], (const float*)d_in[5],
        (const float*)d_in[6], (const float*)d_in[7], (const float*)d_in[8],
        (const float*)d_in[9], (const float*)d_in[10], (const float*)d_in[11],
        (const float*)d_in[12], (const float*)d_in[13], (const float*)d_in[14],
        (const float*)d_in[15], (const float*)d_in[16], (const float*)d_in[17],
        (const float*)d_in[18], (const float*)d_in[19], (const float*)d_in[20],
        (const float*)d_in[21], (const float*)d_in[22], (const float*)d_in[23],
        (const float*)d_in[24], (const float*)d_in[25], (const float*)d_in[26],
        (const float*)d_in[27], (const float*)d_in[28], (const float*)d_in[29],
        (const float*)d_in[30], (float*)d_out);
}

// round 9
// speedup vs baseline: 1.8126x; 1.0014x over previous
#include <cuda_runtime.h>
#include <math.h>
#include <stdint.h>

#define Hd 128
#define Ld 200
#define DTd 768
#define DId 512
#define NTOK 25600
#define TB 64
#define NTH 512

#define O_WH 0
#define O_WL 2560
#define O_AH 8448
#define O_AL 9728
#define O_XH 11008
#define O_XL 15360
#define O_YH 19712
#define O_YL 24064
#define O_GT 28416
#define O_GI 28928
#define O_ID 29440
#define SMEMU 29504

__device__ __forceinline__ uint32_t cvt2(float lo, float hi) {
    uint32_t r;
    asm("cvt.rn.bf16x2.f32 %0, %1, %2;" : "=r"(r) : "f"(hi), "f"(lo));
    return r;
}
__device__ __forceinline__ float blo(uint32_t u) { return __uint_as_float(u << 16); }
__device__ __forceinline__ float bhi(uint32_t u) { return __uint_as_float(u & 0xffff0000u); }

__device__ __forceinline__ void splitq(float4 a, float4 b, uint4& h, uint4& l) {
    h.x = cvt2(a.x, a.y); l.x = cvt2(a.x - blo(h.x), a.y - bhi(h.x));
    h.y = cvt2(a.z, a.w); l.y = cvt2(a.z - blo(h.y), a.w - bhi(h.y));
    h.z = cvt2(b.x, b.y); l.z = cvt2(b.x - blo(h.z), b.y - bhi(h.z));
    h.w = cvt2(b.z, b.w); l.w = cvt2(b.z - blo(h.w), b.w - bhi(h.w));
}

__device__ __forceinline__ void MMA(float* d, uint32_t a0, uint32_t a1, uint32_t a2, uint32_t a3,
                                    uint32_t b0, uint32_t b1) {
    asm volatile("mma.sync.aligned.m16n8k16.row.col.f32.bf16.bf16.f32 "
                 "{%0,%1,%2,%3},{%4,%5,%6,%7},{%8,%9},{%0,%1,%2,%3};"
                 : "+f"(d[0]), "+f"(d[1]), "+f"(d[2]), "+f"(d[3])
                 : "r"(a0), "r"(a1), "r"(a2), "r"(a3), "r"(b0), "r"(b1));
}

__device__ __forceinline__ void zeroD(float D[4][4]) {
#pragma unroll
    for (int n = 0; n < 4; ++n)
#pragma unroll
        for (int j = 0; j < 4; ++j) D[n][j] = 0.f;
}

// weight chunk 128h x 32k (512 threads: one slot each)
__device__ __forceinline__ void w_ldg(const float* __restrict__ W, int ldw, int kc,
                                      int tid, float4 v[2]) {
    int h = tid >> 2, q = tid & 3;
    const float* p = W + (long)h * ldw + kc + q * 8;
    v[0] = *(const float4*)p;
    v[1] = *(const float4*)(p + 4);
}
__device__ __forceinline__ void w_sts(uint32_t* sWh, uint32_t* sWl, int tid, const float4 v[2]) {
    int h = tid >> 2, q = tid & 3;
    uint4 hi, lo;
    splitq(v[0], v[1], hi, lo);
    *(uint4*)(sWh + h * 20 + q * 4) = hi;
    *(uint4*)(sWl + h * 20 + q * 4) = lo;
}
// gathered activation chunk 64tok x 32k (first 256 threads)
__device__ __forceinline__ void ga_ldg(const float* __restrict__ T, int ldw, int kc,
                                       const int* sids, int tid, float4 v[2]) {
    if (tid < 256) {
        int tok = tid >> 2, q = tid & 3;
        const float* p = T + (long)sids[tok] * ldw + kc + q * 8;
        v[0] = *(const float4*)p;
        v[1] = *(const float4*)(p + 4);
    }
}
__device__ __forceinline__ void ga_sts(uint32_t* sAh, uint32_t* sAl, int tid, const float4 v[2]) {
    if (tid < 256) {
        int tok = tid >> 2, q = tid & 3;
        uint4 hi, lo;
        splitq(v[0], v[1], hi, lo);
        *(uint4*)(sAh + tok * 20 + q * 4) = hi;
        *(uint4*)(sAl + tok * 20 + q * 4) = lo;
    }
}

// one KC=32 chunk: warp tile 16h x 32tok (B base pre-offset by token half)
__device__ __forceinline__ void mma_chunk(const uint32_t* __restrict__ Wh, const uint32_t* __restrict__ Wl,
                                          const uint32_t* __restrict__ Bh, const uint32_t* __restrict__ Bl,
                                          int bst, int lane, float D[4][4]) {
    int g = lane >> 2, q = lane & 3;
#pragma unroll
    for (int kt = 0; kt < 2; ++kt) {
        int o = kt * 8 + q;
        uint32_t ah0 = Wh[g * 20 + o], ah1 = Wh[(g + 8) * 20 + o];
        uint32_t ah2 = Wh[g * 20 + o + 4], ah3 = Wh[(g + 8) * 20 + o + 4];
        uint32_t al0 = Wl[g * 20 + o], al1 = Wl[(g + 8) * 20 + o];
        uint32_t al2 = Wl[g * 20 + o + 4], al3 = Wl[(g + 8) * 20 + o + 4];
#pragma unroll
        for (int nt = 0; nt < 4; ++nt) {
            const uint32_t* bp = Bh + (nt * 8 + g) * bst + o;
            const uint32_t* bq = Bl + (nt * 8 + g) * bst + o;
            uint32_t b0 = bp[0], b1 = bp[4];
            uint32_t c0 = bq[0], c1 = bq[4];
            MMA(D[nt], ah0, ah1, ah2, ah3, b0, b1);
            MMA(D[nt], ah0, ah1, ah2, ah3, c0, c1);
            MMA(D[nt], al0, al1, al2, al3, b0, b1);
        }
    }
}

__device__ __forceinline__ void stage_D(float* sWf, float D[4][4], int lane, int hb, int tb) {
    int g = lane >> 2, q = lane & 3;
#pragma unroll
    for (int nt = 0; nt < 4; ++nt) {
        int t0 = tb + nt * 8 + 2 * q;
        float* p0 = sWf + t0 * 132 + hb + g;
        float* p1 = sWf + (t0 + 1) * 132 + hb + g;
        p0[0] = D[nt][0]; p1[0] = D[nt][1]; p0[8] = D[nt][2]; p1[8] = D[nt][3];
    }
}

__device__ __forceinline__ void route8(float* g) {
    float m = g[0];
#pragma unroll
    for (int e = 1; e < 8; ++e) m = fmaxf(m, g[e]);
    float ex[8]; float s = 0.f;
#pragma unroll
    for (int e = 0; e < 8; ++e) { ex[e] = __expf(g[e] - m); s += ex[e]; }
    float inv = 1.f / s;
#pragma unroll
    for (int e = 0; e < 8; ++e) ex[e] *= inv;
    int i1 = 0; float w1 = ex[0];
#pragma unroll
    for (int e = 1; e < 8; ++e) if (ex[e] > w1) { w1 = ex[e]; i1 = e; }
    int i2 = -1; float w2 = -1.f;
#pragma unroll
    for (int e = 0; e < 8; ++e) if (e != i1 && ex[e] > w2) { w2 = ex[e]; i2 = e; }
    float den = 1.f / (w1 + w2 + 1e-8f);
#pragma unroll
    for (int e = 0; e < 8; ++e)
        g[e] = (e == i1) ? w1 * den : ((e == i2) ? w2 * den : 0.f);
}

__global__ __launch_bounds__(NTH, 1)
void sasrec_mma_kernel(
    const int*   __restrict__ input_ids,
    const float* __restrict__ t_noise,   const float* __restrict__ i_noise,
    const float* __restrict__ item_table,const float* __restrict__ pos_table,
    const float* __restrict__ text_table,const float* __restrict__ img_table,
    const float* __restrict__ fc_text_w, const float* __restrict__ fc_text_b,
    const float* __restrict__ fc_img_w,  const float* __restrict__ fc_img_b,
    const float* __restrict__ ln_w,      const float* __restrict__ ln_b,
    const float* __restrict__ mu_t_w,    const float* __restrict__ mu_t_b,
    const float* __restrict__ sg_t_w,    const float* __restrict__ sg_t_b,
    const float* __restrict__ mu_i_w,    const float* __restrict__ mu_i_b,
    const float* __restrict__ sg_i_w,    const float* __restrict__ sg_i_b,
    const float* __restrict__ gate_w,    const float* __restrict__ gate_b,
    const float* __restrict__ texp_w,    const float* __restrict__ texp_b,
    const float* __restrict__ iexp_w,    const float* __restrict__ iexp_b,
    const float* __restrict__ fus_w,     const float* __restrict__ fus_b,
    const float* __restrict__ fus_ln_w,  const float* __restrict__ fus_ln_b,
    float*       __restrict__ out)
{
    extern __shared__ uint32_t su[];
    float*    sWf = (float*)su;
    uint32_t *sWh = su + O_WH, *sWl = su + O_WL;
    uint32_t *sAh = su + O_AH, *sAl = su + O_AL;
    uint32_t *sXh = su + O_XH, *sXl = su + O_XL;
    uint32_t *sYh = su + O_YH, *sYl = su + O_YL;
    float *sgt = (float*)(su + O_GT), *sgi = (float*)(su + O_GI);
    int* sids = (int*)(su + O_ID);

    const int tid = threadIdx.x, lane = tid & 31, wid = tid >> 5;
    const int hb = (wid & 7) * 16;          // h tile
    const int tb = (wid >> 3) * 32;         // token half
    const int n0 = blockIdx.x * TB;
    const int tok = tid >> 3, pq = tid & 7; // epilogue: 8 thr/token, 16 h each

    if (tid < TB) sids[tid] = input_ids[n0 + tid];
    __syncthreads();

    float D[4][4];
    float4 wv[2], av[2];

    // ===== stages 1-2: modality embeddings =====
#pragma unroll 1
    for (int mod = 0; mod < 2; ++mod) {
        const float* tbl = mod ? img_table : text_table;
        const float* Wg  = mod ? fc_img_w : fc_text_w;
        const float* Bb  = mod ? fc_img_b : fc_text_b;
        const int Kd = mod ? DId : DTd;
        uint32_t* szh = mod ? sYh : sXh;
        uint32_t* szl = mod ? sYl : sXl;
        zeroD(D);
        w_ldg(Wg, Kd, 0, tid, wv);
        ga_ldg(tbl, Kd, 0, sids, tid, av);
        const int nck = Kd / 32;
        for (int c = 0; c < nck; ++c) {
            w_sts(sWh, sWl, tid, wv);
            ga_sts(sAh, sAl, tid, av);
            __syncthreads();
            if (c + 1 < nck) {
                w_ldg(Wg, Kd, (c + 1) * 32, tid, wv);
                ga_ldg(tbl, Kd, (c + 1) * 32, sids, tid, av);
            }
            mma_chunk(sWh + hb * 20, sWl + hb * 20, sAh + tb * 20, sAl + tb * 20, 20, lane, D);
            __syncthreads();
        }
        stage_D(sWf, D, lane, hb, tb);
        __syncthreads();
        {
            float v[16]; float ss = 0.f;
#pragma unroll
            for (int j = 0; j < 4; ++j) {
                float4 a = *(const float4*)(sWf + tok * 132 + pq * 16 + j * 4);
                float4 b = *(const float4*)(Bb + pq * 16 + j * 4);
                v[j*4+0] = a.x + b.x; v[j*4+1] = a.y + b.y;
                v[j*4+2] = a.z + b.z; v[j*4+3] = a.w + b.w;
#pragma unroll
                for (int k = 0; k < 4; ++k) ss += v[j*4+k] * v[j*4+k];
            }
            ss += __shfl_xor_sync(0xffffffffu, ss, 1);
            ss += __shfl_xor_sync(0xffffffffu, ss, 2);
            ss += __shfl_xor_sync(0xffffffffu, ss, 4);
            float sc = 1.f / fmaxf(sqrtf(ss), 1e-12f);
#pragma unroll
            for (int j = 0; j < 16; ++j) v[j] *= sc;
#pragma unroll
            for (int j = 0; j < 2; ++j) {
                uint4 hi, lo;
                splitq(*(const float4*)(v + j * 8), *(const float4*)(v + j * 8 + 4), hi, lo);
                *(uint4*)(szh + tok * 68 + pq * 8 + j * 4) = hi;
                *(uint4*)(szl + tok * 68 + pq * 8 + j * 4) = lo;
            }
        }
        __syncthreads();
    }

    // ===== stages 3-4: VAE reparam (mu via out scratch) =====
#pragma unroll 1
    for (int mod = 0; mod < 2; ++mod) {
        const float* muW = mod ? mu_i_w : mu_t_w;
        const float* sgW = mod ? sg_i_w : sg_t_w;
        const float* muB = mod ? mu_i_b : mu_t_b;
        const float* sgB = mod ? sg_i_b : sg_t_b;
        const float* noi = mod ? i_noise : t_noise;
        uint32_t* szh = mod ? sYh : sXh;
        uint32_t* szl = mod ? sYl : sXl;
        zeroD(D);
        w_ldg(muW, Hd, 0, tid, wv);
        for (int c = 0; c < 4; ++c) {
            w_sts(sWh, sWl, tid, wv);
            __syncthreads();
            if (c < 3) w_ldg(muW, Hd, (c + 1) * 32, tid, wv);
            else       w_ldg(sgW, Hd, 0, tid, wv);
            mma_chunk(sWh + hb * 20, sWl + hb * 20,
                      szh + tb * 68 + c * 16, szl + tb * 68 + c * 16, 68, lane, D);
            __syncthreads();
        }
        stage_D(sWf, D, lane, hb, tb);
        __syncthreads();
#pragma unroll
        for (int j = 0; j < 2; ++j) {
            int idx = tid + j * NTH;
            int t = idx >> 4, q = idx & 15;
            float4 a = *(const float4*)(sWf + t * 132 + q * 8);
            float4 b = *(const float4*)(sWf + t * 132 + q * 8 + 4);
            float* p = out + (long)(n0 + t) * Hd + q * 8;
            *(float4*)p = a; *(float4*)(p + 4) = b;
        }
        __syncthreads();
        zeroD(D);
        for (int c = 0; c < 4; ++c) {
            w_sts(sWh, sWl, tid, wv);
            __syncthreads();
            if (c < 3) w_ldg(sgW, Hd, (c + 1) * 32, tid, wv);
            mma_chunk(sWh + hb * 20, sWl + hb * 20,
                      szh + tb * 68 + c * 16, szl + tb * 68 + c * 16, 68, lane, D);
            __syncthreads();
        }
        stage_D(sWf, D, lane, hb, tb);
        __syncthreads();
        {
            long n = n0 + tok;
#pragma unroll
            for (int j = 0; j < 2; ++j) {
                int o = pq * 16 + j * 8;
                float z[8];
#pragma unroll
                for (int k = 0; k < 8; ++k) {
                    float sg = sWf[tok * 132 + o + k];
                    float mu = out[n * Hd + o + k];
                    z[k] = mu + muB[o + k] + __expf(sg + sgB[o + k]) * noi[n * Hd + o + k];
                }
                uint4 hi, lo;
                splitq(*(const float4*)z, *(const float4*)(z + 4), hi, lo);
                *(uint4*)(szh + tok * 68 + pq * 8 + j * 4) = hi;
                *(uint4*)(szl + tok * 68 + pq * 8 + j * 4) = lo;
            }
        }
        __syncthreads();
    }

    // ===== stage 5: gating (one (token, expert) per thread) =====
    {
        int t = tok, e = pq;
        float dt = 0.f, di = 0.f;
        const uint32_t *xh = sXh + t * 68, *xl = sXl + t * 68;
        const uint32_t *yh = sYh + t * 68, *yl = sYl + t * 68;
        const float* gw = gate_w + e * Hd;
#pragma unroll 4
        for (int k4 = 0; k4 < 64; k4 += 4) {
#pragma unroll
            for (int j = 0; j < 4; ++j) {
                uint32_t a = xh[k4 + j], b = xl[k4 + j];
                uint32_t c = yh[k4 + j], d = yl[k4 + j];
                float zx0 = blo(a) + blo(b), zx1 = bhi(a) + bhi(b);
                float zy0 = blo(c) + blo(d), zy1 = bhi(c) + bhi(d);
                float w0 = gw[(k4 + j) * 2], w1 = gw[(k4 + j) * 2 + 1];
                dt = fmaf(zx0, w0, fmaf(zx1, w1, dt));
                di = fmaf(zy0, w0, fmaf(zy1, w1, di));
            }
        }
        sgt[t * 8 + e] = dt + gate_b[e];
        sgi[t * 8 + e] = di + gate_b[e];
    }
    __syncthreads();
    if (tid < TB) { route8(sgt + tid * 8); route8(sgi + tid * 8); }
    __syncthreads();

    // ===== stages 6-7: dense experts, gate folded =====
#pragma unroll 1
    for (int mod = 0; mod < 2; ++mod) {
        const float* eW = mod ? iexp_w : texp_w;
        const float* eB = mod ? iexp_b : texp_b;
        const float* gs = mod ? sgi : sgt;
        uint32_t* szh = mod ? sYh : sXh;
        uint32_t* szl = mod ? sYl : sXl;
        float acc[4][4];
        zeroD(acc); zeroD(D);
        w_ldg(eW, Hd, 0, tid, wv);
#pragma unroll 1
        for (int e = 0; e < 8; ++e) {
#pragma unroll 1
            for (int c = 0; c < 4; ++c) {
                w_sts(sWh, sWl, tid, wv);
                __syncthreads();
                if (!(e == 7 && c == 3)) {
                    const float* nw = (c < 3) ? eW + (long)e * Hd * Hd : eW + (long)(e + 1) * Hd * Hd;
                    w_ldg(nw, Hd, (c < 3) ? (c + 1) * 32 : 0, tid, wv);
                }
                mma_chunk(sWh + hb * 20, sWl + hb * 20,
                          szh + tb * 68 + c * 16, szl + tb * 68 + c * 16, 68, lane, D);
                __syncthreads();
            }
            int g = lane >> 2, q = lane & 3;
            float b0 = eB[e * Hd + hb + g], b1 = eB[e * Hd + hb + g + 8];
#pragma unroll
            for (int nt = 0; nt < 4; ++nt) {
                int t0 = tb + nt * 8 + 2 * q;
                float g0 = gs[t0 * 8 + e], g1 = gs[(t0 + 1) * 8 + e];
                acc[nt][0] += g0 * (D[nt][0] + b0);
                acc[nt][1] += g1 * (D[nt][1] + b0);
                acc[nt][2] += g0 * (D[nt][2] + b1);
                acc[nt][3] += g1 * (D[nt][3] + b1);
                D[nt][0] = D[nt][1] = D[nt][2] = D[nt][3] = 0.f;
            }
        }
        stage_D(sWf, acc, lane, hb, tb);
        __syncthreads();
#pragma unroll
        for (int j = 0; j < 2; ++j) {
            uint4 hi, lo;
            splitq(*(const float4*)(sWf + tok * 132 + pq * 16 + j * 8),
                   *(const float4*)(sWf + tok * 132 + pq * 16 + j * 8 + 4), hi, lo);
            *(uint4*)(szh + tok * 68 + pq * 8 + j * 4) = hi;
            *(uint4*)(szl + tok * 68 + pq * 8 + j * 4) = lo;
        }
        __syncthreads();
    }

    // ===== stage 8: fusion + LN/relu + seq_emb =====
    zeroD(D);
    w_ldg(fus_w, 2 * Hd, 0, tid, wv);
    for (int c = 0; c < 8; ++c) {
        w_sts(sWh, sWl, tid, wv);
        __syncthreads();
        if (c < 7) w_ldg(fus_w, 2 * Hd, (c + 1) * 32, tid, wv);
        const uint32_t* Bh = (c < 4) ? sXh + c * 16 : sYh + (c - 4) * 16;
        const uint32_t* Bl = (c < 4) ? sXl + c * 16 : sYl + (c - 4) * 16;
        mma_chunk(sWh + hb * 20, sWl + hb * 20, Bh + tb * 68, Bl + tb * 68, 68, lane, D);
        __syncthreads();
    }
    stage_D(sWf, D, lane, hb, tb);
    __syncthreads();
    {
        long n = n0 + tok;
        float v[16]; float s = 0.f, s2 = 0.f;
#pragma unroll
        for (int j = 0; j < 4; ++j) {
            float4 a = *(const float4*)(sWf + tok * 132 + pq * 16 + j * 4);
            float4 b = *(const float4*)(fus_b + pq * 16 + j * 4);
            v[j*4+0] = a.x + b.x; v[j*4+1] = a.y + b.y;
            v[j*4+2] = a.z + b.z; v[j*4+3] = a.w + b.w;
#pragma unroll
            for (int k = 0; k < 4; ++k) { s += v[j*4+k]; s2 += v[j*4+k] * v[j*4+k]; }
        }
        s  += __shfl_xor_sync(0xffffffffu, s, 1);  s  += __shfl_xor_sync(0xffffffffu, s, 2);
        s  += __shfl_xor_sync(0xffffffffu, s, 4);
        s2 += __shfl_xor_sync(0xffffffffu, s2, 1); s2 += __shfl_xor_sync(0xffffffffu, s2, 2);
        s2 += __shfl_xor_sync(0xffffffffu, s2, 4);
        float mean = s * (1.f / Hd);
        float var  = s2 * (1.f / Hd) - mean * mean;
        float inv  = rsqrtf(var + 1e-5f);
        int id = sids[tok], pos = (int)(n % Ld);
        float w[16]; float t1 = 0.f, t2 = 0.f;
#pragma unroll
        for (int j = 0; j < 4; ++j) {
            float4 a = *(const float4*)(item_table + (long)id * Hd + pq * 16 + j * 4);
            float4 b = *(const float4*)(pos_table + pos * Hd + pq * 16 + j * 4);
            w[j*4+0] = a.x + b.x; w[j*4+1] = a.y + b.y;
            w[j*4+2] = a.z + b.z; w[j*4+3] = a.w + b.w;
#pragma unroll
            for (int k = 0; k < 4; ++k) { t1 += w[j*4+k]; t2 += w[j*4+k] * w[j*4+k]; }
        }
        t1 += __shfl_xor_sync(0xffffffffu, t1, 1); t1 += __shfl_xor_sync(0xffffffffu, t1, 2);
        t1 += __shfl_xor_sync(0xffffffffu, t1, 4);
        t2 += __shfl_xor_sync(0xffffffffu, t2, 1); t2 += __shfl_xor_sync(0xffffffffu, t2, 2);
        t2 += __shfl_xor_sync(0xffffffffu, t2, 4);
        float mean2 = t1 * (1.f / Hd);
        float var2  = t2 * (1.f / Hd) - mean2 * mean2;
        float inv2  = rsqrtf(var2 + 1e-12f);
#pragma unroll
        for (int j = 0; j < 4; ++j) {
            int o = pq * 16 + j * 4;
            float4 lw  = *(const float4*)(fus_ln_w + o);
            float4 lb  = *(const float4*)(fus_ln_b + o);
            float4 slw = *(const float4*)(ln_w + o);
            float4 slb = *(const float4*)(ln_b + o);
            float4 r;
            r.x = fmaxf((v[j*4+0] - mean) * inv * lw.x + lb.x, 0.f) + (w[j*4+0] - mean2) * inv2 * slw.x + slb.x;
            r.y = fmaxf((v[j*4+1] - mean) * inv * lw.y + lb.y, 0.f) + (w[j*4+1] - mean2) * inv2 * slw.y + slb.y;
            r.z = fmaxf((v[j*4+2] - mean) * inv * lw.z + lb.z, 0.f) + (w[j*4+2] - mean2) * inv2 * slw.z + slb.z;
            r.w = fmaxf((v[j*4+3] - mean) * inv * lw.w + lb.w, 0.f) + (w[j*4+3] - mean2) * inv2 * slw.w + slb.w;
            *(float4*)(out + n * Hd + o) = r;
        }
    }
}

extern "C" void kernel_launch(void* const* d_in, const int* in_sizes, int n_in,
                              void* d_out, int out_size) {
    (void)in_sizes; (void)n_in; (void)out_size;
    size_t smem = SMEMU * sizeof(uint32_t);
    cudaFuncSetAttribute(sasrec_mma_kernel,
                         cudaFuncAttributeMaxDynamicSharedMemorySize, (int)smem);
    sasrec_mma_kernel<<<NTOK / TB, NTH, smem>>>(
        (const int*)d_in[0], (const float*)d_in[1], (const float*)d_in[2],
        (const float*)d_in[3], (const float*)d_in[4], (const float*)d_in[5],
        (const float*)d_in[6], (const float*)d_in[7], (const float*)d_in[8],
        (const float*)d_in[9], (const float*)d_in[10], (const float*)d_in[11],
        (const float*)d_in[12], (const float*)d_in[13], (const float*)d_in[14],
        (const float*)d_in[15], (const float*)d_in[16], (const float*)d_in[17],
        (const float*)d_in[18], (const float*)d_in[19], (const float*)d_in[20],
        (const float*)d_in[21], (const float*)d_in[22], (const float*)d_in[23],
        (const float*)d_in[24], (const float*)d_in[25], (const float*)d_in[26],
        (const float*)d_in[27], (const float*)d_in[28], (const float*)d_in[29],
        (const float*)d_in[30], (float*)d_out);
}